// round 9
// baseline (speedup 1.0000x reference)
#include <cuda_runtime.h>
#include <cstdint>

#define N_NODE 100000        // N_USER == N_ITEM == 100000
#define NEDGE  1000000
#define C      128
#define CC     (C * C)
#define NC     ((size_t)N_NODE * C)

// ---------------- device scratch (allowed: __device__ globals) ----------------
__device__ __align__(16) float g_xu[NC];            // user features after layer 0
__device__ __align__(16) float g_xi[NC];            // item features after layer 0
__device__ __align__(16) int   g_cnt[3 * N_NODE];
__device__ __align__(16) float g_inv[3 * N_NODE];
__device__ __align__(16) float g_wsum[2 * CC];      // Wr[l,1]+Wr[l,2] per layer
__device__ __align__(16) int   g_rowptr[3 * (N_NODE + 1)];
__device__ __align__(16) int   g_colidx[3 * NEDGE];
__device__ __align__(16) int   g_cur[3 * N_NODE];

// ---------------- tiny utility kernels ----------------
__global__ void zero_k(float4* __restrict__ p, long n4) {
    long i = (long)blockIdx.x * blockDim.x + threadIdx.x;
    long st = (long)gridDim.x * blockDim.x;
    float4 z = make_float4(0.f, 0.f, 0.f, 0.f);
    for (; i < n4; i += st) p[i] = z;
}

__global__ void count_k(const int* __restrict__ dst, int* __restrict__ cnt, int E) {
    int i = blockIdx.x * blockDim.x + threadIdx.x;
    int st = gridDim.x * blockDim.x;
    for (; i < E; i += st) atomicAdd(cnt + dst[i], 1);
}

__global__ void inv_k(const int* __restrict__ cnt, float* __restrict__ inv, int n) {
    int i = blockIdx.x * blockDim.x + threadIdx.x;
    if (i < n) {
        int c = cnt[i];
        inv[i] = 1.0f / (float)(c > 1 ? c : 1);
    }
}

__global__ void addW_k(const float* __restrict__ a, const float* __restrict__ b,
                       float* __restrict__ o, int n) {
    int i = blockIdx.x * blockDim.x + threadIdx.x;
    if (i < n) o[i] = a[i] + b[i];
}

// exclusive scan of one edge type's counts -> rowptr. One block per type.
#define SCAN_T 1024
__global__ void __launch_bounds__(SCAN_T) scan_k(const int* __restrict__ cnt,
                                                 int* __restrict__ rowptr) {
    int type = blockIdx.x;
    const int* c = cnt + type * N_NODE;
    int* rp = rowptr + type * (N_NODE + 1);
    __shared__ int part[SCAN_T];
    int t = threadIdx.x;
    const int chunk = (N_NODE + SCAN_T - 1) / SCAN_T;   // 98
    int beg = t * chunk;
    int end = beg + chunk; if (end > N_NODE) end = N_NODE;
    int s = 0;
    for (int i = beg; i < end; ++i) s += c[i];
    part[t] = s;
    __syncthreads();
    for (int off = 1; off < SCAN_T; off <<= 1) {
        int v = (t >= off) ? part[t - off] : 0;
        __syncthreads();
        part[t] += v;
        __syncthreads();
    }
    int prefix = (t == 0) ? 0 : part[t - 1];
    for (int i = beg; i < end; ++i) {
        rp[i] = prefix;
        prefix += c[i];
    }
    if (t == SCAN_T - 1) rp[N_NODE] = prefix;
}

__global__ void fill_k(const int* __restrict__ ei, const int* __restrict__ rowptr,
                       int* __restrict__ cur, int* __restrict__ col, int E) {
    int i = blockIdx.x * blockDim.x + threadIdx.x;
    int st = gridDim.x * blockDim.x;
    for (; i < E; i += st) {
        int s = ei[i];
        int d = ei[E + i];
        int pos = rowptr[d] + atomicAdd(cur + d, 1);
        col[pos] = s;
    }
}

// ================ tf32 mma.sync GEMM (gather-fused) + bias + LN + ReLU ================
// D[m,n] = sum_terms (mean-or-x)_t[m,:] @ W_t[:,n], CTA tile 128x128, K=128.
// 8 warps in 2M x 4N; each warp 64x32 via m16n8k8.row.col.f32.tf32.tf32.f32.
// Mean terms gather neighbor rows via CSR and accumulate in registers (no agg array).
// Fragment smem layouts are padded (A: 1028/ks, B: 68/nt) -> STS conflicts 2-way.

__device__ __forceinline__ uint32_t f2tf32(float x) {
    uint32_t o; asm("cvt.rna.tf32.f32 %0, %1;" : "=r"(o) : "f"(x)); return o;
}

#define MMA_TF32(d, a, b)                                                       \
    asm volatile("mma.sync.aligned.m16n8k8.row.col.f32.tf32.tf32.f32 "          \
                 "{%0,%1,%2,%3}, {%4,%5,%6,%7}, {%8,%9}, {%0,%1,%2,%3};"        \
                 : "+f"((d)[0]), "+f"((d)[1]), "+f"((d)[2]), "+f"((d)[3])       \
                 : "r"((a).x), "r"((a).y), "r"((a).z), "r"((a).w),              \
                   "r"((b).x), "r"((b).y))

// SMEM layout (bytes)
#define SM_A      0          // 16 ks x 1028 uint32 = 65792 B
#define SM_B      65792      // 16 ks x 16 nt x 68 uint32 = 69632 B
#define SM_PART   135424     // 128 rows x 4 warps x float2 = 4KB
#define SM_STAT   139520     // 128 x float2 (mu, rs) = 1KB
#define SM_BIAS   140544     // 128 f32
#define SM_LNW    141056
#define SM_LNB    141568
#define GEMM_SMEM 142080

#define GEMM_GRID 782        // ceil(100000 / 128)

// Fragment address math (logical layout identical to round 8, strides padded):
// A uint32 idx = ks*1028 + mt*128 + (m&7)*16 + e*4 + slot,
//   slot = ((m>>3)&1) | (((k>>2)&1)<<1), ks=k>>3, mt=m>>4, e=k&3.
// B uint32 idx = (ks*16+nt)*68 + (n&7)*8 + (k&3)*2 + ((k>>2)&1).

// regular A term: read rows of A, scale by optional inv, store fragments
__device__ __forceinline__ void stage_A(uint32_t* sA, const float* __restrict__ A,
                                        int nodeBase, int N, int t)
{
#pragma unroll 4
    for (int i = 0; i < 16; ++i) {
        int f = t + i * 256;              // 0..4095 float4 slots; m=f>>5, k4=f&31
        int m = f >> 5, k4 = f & 31;
        int node = nodeBase + m;
        float4 v = make_float4(0.f, 0.f, 0.f, 0.f);
        if (node < N) v = __ldg((const float4*)(A + (size_t)node * C) + k4);
        int ks = k4 >> 1;
        int mt = m >> 4;
        int slot = ((m >> 3) & 1) | ((k4 & 1) << 1);
        int base = ks * 1028 + mt * 128 + ((m & 7) << 4) + slot;
        sA[base + 0 * 4] = f2tf32(v.x);
        sA[base + 1 * 4] = f2tf32(v.y);
        sA[base + 2 * 4] = f2tf32(v.z);
        sA[base + 3 * 4] = f2tf32(v.w);
    }
}

// gather (mean) A term: warp w handles rows w*16..w*16+15; lane = float4 column k4
__device__ __forceinline__ void stage_A_gather(uint32_t* sA, const float* __restrict__ X,
                                               const int* __restrict__ rowptr,
                                               const int* __restrict__ colidx,
                                               const float* __restrict__ inv,
                                               int nodeBase, int N, int warp, int lane)
{
#pragma unroll 1
    for (int r = 0; r < 16; ++r) {
        int m = warp * 16 + r;
        int node = nodeBase + m;
        float4 v = make_float4(0.f, 0.f, 0.f, 0.f);
        if (node < N) {
            int beg = __ldg(rowptr + node);
            int end = __ldg(rowptr + node + 1);
            float4 v2 = make_float4(0.f, 0.f, 0.f, 0.f);
            int j = beg;
            for (; j + 1 < end; j += 2) {
                int s0 = __ldg(colidx + j);
                int s1 = __ldg(colidx + j + 1);
                float4 a = __ldg((const float4*)(X + (size_t)s0 * C) + lane);
                float4 b = __ldg((const float4*)(X + (size_t)s1 * C) + lane);
                v.x += a.x;  v.y += a.y;  v.z += a.z;  v.w += a.w;
                v2.x += b.x; v2.y += b.y; v2.z += b.z; v2.w += b.w;
            }
            if (j < end) {
                int s0 = __ldg(colidx + j);
                float4 a = __ldg((const float4*)(X + (size_t)s0 * C) + lane);
                v.x += a.x; v.y += a.y; v.z += a.z; v.w += a.w;
            }
            v.x += v2.x; v.y += v2.y; v.z += v2.z; v.w += v2.w;
            float sc = __ldg(inv + node);
            v.x *= sc; v.y *= sc; v.z *= sc; v.w *= sc;
        }
        int k4 = lane;
        int ks = k4 >> 1;
        int mt = m >> 4;
        int slot = ((m >> 3) & 1) | ((k4 & 1) << 1);
        int base = ks * 1028 + mt * 128 + ((m & 7) << 4) + slot;
        sA[base + 0 * 4] = f2tf32(v.x);
        sA[base + 1 * 4] = f2tf32(v.y);
        sA[base + 2 * 4] = f2tf32(v.z);
        sA[base + 3 * 4] = f2tf32(v.w);
    }
}

// B = W [128k x 128n] row-major -> fragment order
__device__ __forceinline__ void stage_B(uint32_t* sB, const float* __restrict__ W, int t)
{
#pragma unroll 4
    for (int i = 0; i < 16; ++i) {
        int f = t + i * 256;              // k=f>>5, n4=f&31
        int k = f >> 5, n4 = f & 31;
        float4 w = __ldg((const float4*)W + f);
        int ks = k >> 3;
        int nt = n4 >> 1;
        int slot = (k >> 2) & 1;
        int n0_7 = (n4 & 1) << 2;
        int base = (ks * 16 + nt) * 68 + (k & 3) * 2 + slot;
        sB[base + (n0_7 + 0) * 8] = f2tf32(w.x);
        sB[base + (n0_7 + 1) * 8] = f2tf32(w.y);
        sB[base + (n0_7 + 2) * 8] = f2tf32(w.z);
        sB[base + (n0_7 + 3) * 8] = f2tf32(w.w);
    }
}

template <int NTERMS>
__global__ void __launch_bounds__(256) gemm_mma(
    const float* __restrict__ A0, const int* __restrict__ rp0, const int* __restrict__ ci0,
    const float* __restrict__ inv0, const float* __restrict__ W0,
    const float* __restrict__ A1, const int* __restrict__ rp1, const int* __restrict__ ci1,
    const float* __restrict__ inv1, const float* __restrict__ W1,
    const float* __restrict__ A2, const int* __restrict__ rp2, const int* __restrict__ ci2,
    const float* __restrict__ inv2, const float* __restrict__ W2,
    const float* __restrict__ bias0, const float* __restrict__ bias1,
    const float* __restrict__ lnw, const float* __restrict__ lnb,
    float* __restrict__ out, int N)
{
    extern __shared__ char smem[];
    uint32_t* sA = (uint32_t*)(smem + SM_A);
    uint32_t* sB = (uint32_t*)(smem + SM_B);
    float2* sPart = (float2*)(smem + SM_PART);
    float2* sStat = (float2*)(smem + SM_STAT);
    float* sBias  = (float*)(smem + SM_BIAS);
    float* sLnw   = (float*)(smem + SM_LNW);
    float* sLnb   = (float*)(smem + SM_LNB);

    const int t = threadIdx.x;
    const int warp = t >> 5;
    const int lane = t & 31;
    const int wm = warp >> 2;     // 0..1  (M half)
    const int wn = warp & 3;      // 0..3  (N quarter)
    const int nodeBase = blockIdx.x * 128;

    if (t < 128) {
        float b = bias0 ? __ldg(bias0 + t) : 0.f;
        if (bias1) b += __ldg(bias1 + t);
        sBias[t] = b;
        sLnw[t] = __ldg(lnw + t);
        sLnb[t] = __ldg(lnb + t);
    }

    const float* As[3]   = {A0, A1, A2};
    const int*   rps[3]  = {rp0, rp1, rp2};
    const int*   cis[3]  = {ci0, ci1, ci2};
    const float* invs[3] = {inv0, inv1, inv2};
    const float* Ws[3]   = {W0, W1, W2};

    float acc[4][4][4];
#pragma unroll
    for (int a = 0; a < 4; ++a)
#pragma unroll
        for (int b = 0; b < 4; ++b)
#pragma unroll
            for (int c = 0; c < 4; ++c) acc[a][b][c] = 0.f;

    const uint4* sA4 = (const uint4*)sA;
    const uint2* sB2 = (const uint2*)sB;

#pragma unroll 1
    for (int term = 0; term < NTERMS; ++term) {
        if (term > 0) __syncthreads();    // all warps done reading previous tiles
        if (rps[term]) {
            stage_A_gather(sA, As[term], rps[term], cis[term], invs[term],
                           nodeBase, N, warp, lane);
        } else {
            stage_A(sA, As[term], nodeBase, N, t);
        }
        stage_B(sB, Ws[term], t);
        __syncthreads();

#pragma unroll 1
        for (int ks = 0; ks < 16; ++ks) {
            uint4 af[4];
            uint2 bf[4];
#pragma unroll
            for (int mt = 0; mt < 4; ++mt)
                af[mt] = sA4[ks * 257 + (wm * 4 + mt) * 32 + lane];
#pragma unroll
            for (int nt = 0; nt < 4; ++nt)
                bf[nt] = sB2[(ks * 16 + wn * 4 + nt) * 34 + lane];
#pragma unroll
            for (int mt = 0; mt < 4; ++mt)
#pragma unroll
                for (int nt = 0; nt < 4; ++nt)
                    MMA_TF32(acc[mt][nt], af[mt], bf[nt]);
        }
    }

    // ---------------- epilogue: bias + LayerNorm + ReLU ----------------
    // Thread owns rows (wm*4+mt)*16 + hi*8 + lane/4, cols (wn*4+nt)*8 + (lane&3)*2 + e.
#pragma unroll
    for (int mt = 0; mt < 4; ++mt) {
#pragma unroll
        for (int hi = 0; hi < 2; ++hi) {
            float s = 0.f, q = 0.f;
#pragma unroll
            for (int nt = 0; nt < 4; ++nt) {
#pragma unroll
                for (int e = 0; e < 2; ++e) {
                    int col = (wn * 4 + nt) * 8 + (lane & 3) * 2 + e;
                    float v = acc[mt][nt][hi * 2 + e] + sBias[col];
                    s += v; q += v * v;
                }
            }
            s += __shfl_xor_sync(0xffffffffu, s, 1);
            q += __shfl_xor_sync(0xffffffffu, q, 1);
            s += __shfl_xor_sync(0xffffffffu, s, 2);
            q += __shfl_xor_sync(0xffffffffu, q, 2);
            if ((lane & 3) == 0) {
                int row = (wm * 4 + mt) * 16 + hi * 8 + (lane >> 2);
                sPart[row * 4 + wn] = make_float2(s, q);
            }
        }
    }
    __syncthreads();
    if (t < 128) {
        float2 p0 = sPart[t * 4 + 0], p1 = sPart[t * 4 + 1];
        float2 p2 = sPart[t * 4 + 2], p3 = sPart[t * 4 + 3];
        float s = p0.x + p1.x + p2.x + p3.x;
        float q = p0.y + p1.y + p2.y + p3.y;
        float mu = s * (1.0f / C);
        float var = q * (1.0f / C) - mu * mu;
        sStat[t] = make_float2(mu, rsqrtf(var + 1e-5f));
    }
    __syncthreads();

#pragma unroll
    for (int mt = 0; mt < 4; ++mt) {
#pragma unroll
        for (int hi = 0; hi < 2; ++hi) {
            int row = (wm * 4 + mt) * 16 + hi * 8 + (lane >> 2);
            int node = nodeBase + row;
            if (node < N) {
                float2 st = sStat[row];
#pragma unroll
                for (int nt = 0; nt < 4; ++nt) {
                    int col = (wn * 4 + nt) * 8 + (lane & 3) * 2;
                    float v0 = acc[mt][nt][hi * 2 + 0] + sBias[col];
                    float v1 = acc[mt][nt][hi * 2 + 1] + sBias[col + 1];
                    float2 o;
                    o.x = fmaxf((v0 - st.x) * st.y * sLnw[col]     + sLnb[col],     0.f);
                    o.y = fmaxf((v1 - st.x) * st.y * sLnw[col + 1] + sLnb[col + 1], 0.f);
                    *(float2*)(out + (size_t)node * C + col) = o;
                }
            }
        }
    }
}

// ---------------- host launcher ----------------
extern "C" void kernel_launch(void* const* d_in, const int* in_sizes, int n_in,
                              void* d_out, int out_size)
{
    const float* x_user = (const float*)d_in[0];
    const float* x_item = (const float*)d_in[1];
    const int*   ei_ui  = (const int*)d_in[2];
    const int*   ei_iu  = (const int*)d_in[3];
    const int*   ei_uu  = (const int*)d_in[4];
    const float* Wl     = (const float*)d_in[5];
    const float* bl     = (const float*)d_in[6];
    const float* Wr     = (const float*)d_in[7];
    const float* ln_w   = (const float*)d_in[8];
    const float* ln_b   = (const float*)d_in[9];
    float* out = (float*)d_out;

    void *pxu_, *pxi_, *pcnt_, *pinv_, *pws_, *prp_, *pci_, *pcur_;
    cudaGetSymbolAddress(&pxu_, g_xu);
    cudaGetSymbolAddress(&pxi_, g_xi);
    cudaGetSymbolAddress(&pcnt_, g_cnt);
    cudaGetSymbolAddress(&pinv_, g_inv);
    cudaGetSymbolAddress(&pws_, g_wsum);
    cudaGetSymbolAddress(&prp_, g_rowptr);
    cudaGetSymbolAddress(&pci_, g_colidx);
    cudaGetSymbolAddress(&pcur_, g_cur);
    float* pxu  = (float*)pxu_;
    float* pxi  = (float*)pxi_;
    int*   pcnt = (int*)pcnt_;
    float* pinv = (float*)pinv_;
    float* pws  = (float*)pws_;
    int*   prp  = (int*)prp_;
    int*   pci  = (int*)pci_;
    int*   pcur = (int*)pcur_;

    cudaFuncSetAttribute((const void*)gemm_mma<2>,
                         cudaFuncAttributeMaxDynamicSharedMemorySize, GEMM_SMEM);
    cudaFuncSetAttribute((const void*)gemm_mma<3>,
                         cudaFuncAttributeMaxDynamicSharedMemorySize, GEMM_SMEM);

    // ---- CSR build (edges identical across layers: once per call) ----
    zero_k<<<128, 256>>>((float4*)pcnt, (long)(3 * N_NODE) / 4);
    zero_k<<<128, 256>>>((float4*)pcur, (long)(3 * N_NODE) / 4);
    count_k<<<2048, 256>>>(ei_ui + NEDGE, pcnt + 0 * N_NODE, NEDGE);
    count_k<<<2048, 256>>>(ei_iu + NEDGE, pcnt + 1 * N_NODE, NEDGE);
    count_k<<<2048, 256>>>(ei_uu + NEDGE, pcnt + 2 * N_NODE, NEDGE);
    inv_k<<<(3 * N_NODE + 255) / 256, 256>>>(pcnt, pinv, 3 * N_NODE);
    scan_k<<<3, SCAN_T>>>(pcnt, prp);
    fill_k<<<2048, 256>>>(ei_ui, prp + 0 * (N_NODE + 1), pcur + 0 * N_NODE,
                          pci + 0 * NEDGE, NEDGE);
    fill_k<<<2048, 256>>>(ei_iu, prp + 1 * (N_NODE + 1), pcur + 1 * N_NODE,
                          pci + 1 * NEDGE, NEDGE);
    fill_k<<<2048, 256>>>(ei_uu, prp + 2 * (N_NODE + 1), pcur + 2 * N_NODE,
                          pci + 2 * NEDGE, NEDGE);

    // Wsum[l] = Wr[l,1] + Wr[l,2]  (fold the two xu @ Wr terms into one GEMM term)
    for (int l = 0; l < 2; ++l)
        addW_k<<<(CC + 255) / 256, 256>>>(Wr + (size_t)(l * 3 + 1) * CC,
                                          Wr + (size_t)(l * 3 + 2) * CC,
                                          pws + (size_t)l * CC, CC);

    for (int l = 0; l < 2; ++l) {
        const float* xu_src = (l == 0) ? x_user : pxu;
        const float* xi_src = (l == 0) ? x_item : pxi;
        float* outu = (l == 0) ? pxu : out;
        float* outi = (l == 0) ? pxi : out + NC;

        // item: gather-mean(xu over ui) @ Wl[l,0] + bl[l,0] + xi @ Wr[l,0] -> LN -> ReLU
        gemm_mma<2><<<GEMM_GRID, 256, GEMM_SMEM>>>(
            xu_src, prp + 0 * (N_NODE + 1), pci + 0 * NEDGE, pinv + 0 * N_NODE,
            Wl + (size_t)(l * 3 + 0) * CC,
            xi_src, nullptr, nullptr, nullptr,
            Wr + (size_t)(l * 3 + 0) * CC,
            nullptr, nullptr, nullptr, nullptr, nullptr,
            bl + (size_t)(l * 3 + 0) * C, nullptr,
            ln_w + (size_t)(l * 2 + 1) * C, ln_b + (size_t)(l * 2 + 1) * C,
            outi, N_NODE);

        // user: gather-mean(xi over iu)@Wl[l,1] + gather-mean(xu over uu)@Wl[l,2]
        //     + xu @ (Wr[l,1]+Wr[l,2]) + bl[l,1]+bl[l,2] -> LN -> ReLU
        gemm_mma<3><<<GEMM_GRID, 256, GEMM_SMEM>>>(
            xi_src, prp + 1 * (N_NODE + 1), pci + 1 * NEDGE, pinv + 1 * N_NODE,
            Wl + (size_t)(l * 3 + 1) * CC,
            xu_src, prp + 2 * (N_NODE + 1), pci + 2 * NEDGE, pinv + 2 * N_NODE,
            Wl + (size_t)(l * 3 + 2) * CC,
            xu_src, nullptr, nullptr, nullptr,
            pws + (size_t)l * CC,
            bl + (size_t)(l * 3 + 1) * C, bl + (size_t)(l * 3 + 2) * C,
            ln_w + (size_t)(l * 2 + 0) * C, ln_b + (size_t)(l * 2 + 0) * C,
            outu, N_NODE);
    }
}

// round 10
// speedup vs baseline: 1.6445x; 1.6445x over previous
#include <cuda_runtime.h>
#include <cstdint>

#define N_NODE 100000        // N_USER == N_ITEM == 100000
#define NEDGE  1000000
#define C      128
#define CC     (C * C)
#define NC     ((size_t)N_NODE * C)

// ---------------- device scratch (allowed: __device__ globals) ----------------
__device__ __align__(16) float g_xu[NC];            // user features after layer 0
__device__ __align__(16) float g_xi[NC];            // item features after layer 0
__device__ __align__(16) float g_agg[3][NC];        // gathered means per edge type
__device__ __align__(16) int   g_cnt[3 * N_NODE];
__device__ __align__(16) float g_inv[3 * N_NODE];
__device__ __align__(16) float g_wsum[2 * CC];      // Wr[l,1]+Wr[l,2] per layer
__device__ __align__(16) int   g_rowptr[3 * (N_NODE + 1)];
__device__ __align__(16) int   g_colidx[3 * NEDGE];
__device__ __align__(16) int   g_cur[3 * N_NODE];

// ---------------- tiny utility kernels ----------------
__global__ void zero_k(float4* __restrict__ p, long n4) {
    long i = (long)blockIdx.x * blockDim.x + threadIdx.x;
    long st = (long)gridDim.x * blockDim.x;
    float4 z = make_float4(0.f, 0.f, 0.f, 0.f);
    for (; i < n4; i += st) p[i] = z;
}

__global__ void count_k(const int* __restrict__ dst, int* __restrict__ cnt, int E) {
    int i = blockIdx.x * blockDim.x + threadIdx.x;
    int st = gridDim.x * blockDim.x;
    for (; i < E; i += st) atomicAdd(cnt + dst[i], 1);
}

__global__ void inv_k(const int* __restrict__ cnt, float* __restrict__ inv, int n) {
    int i = blockIdx.x * blockDim.x + threadIdx.x;
    if (i < n) {
        int c = cnt[i];
        inv[i] = 1.0f / (float)(c > 1 ? c : 1);
    }
}

__global__ void addW_k(const float* __restrict__ a, const float* __restrict__ b,
                       float* __restrict__ o, int n) {
    int i = blockIdx.x * blockDim.x + threadIdx.x;
    if (i < n) o[i] = a[i] + b[i];
}

// exclusive scan of one edge type's counts -> rowptr. One block per type.
#define SCAN_T 1024
__global__ void __launch_bounds__(SCAN_T) scan_k(const int* __restrict__ cnt,
                                                 int* __restrict__ rowptr) {
    int type = blockIdx.x;
    const int* c = cnt + type * N_NODE;
    int* rp = rowptr + type * (N_NODE + 1);
    __shared__ int part[SCAN_T];
    int t = threadIdx.x;
    const int chunk = (N_NODE + SCAN_T - 1) / SCAN_T;   // 98
    int beg = t * chunk;
    int end = beg + chunk; if (end > N_NODE) end = N_NODE;
    int s = 0;
    for (int i = beg; i < end; ++i) s += c[i];
    part[t] = s;
    __syncthreads();
    for (int off = 1; off < SCAN_T; off <<= 1) {
        int v = (t >= off) ? part[t - off] : 0;
        __syncthreads();
        part[t] += v;
        __syncthreads();
    }
    int prefix = (t == 0) ? 0 : part[t - 1];
    for (int i = beg; i < end; ++i) {
        rp[i] = prefix;
        prefix += c[i];
    }
    if (t == SCAN_T - 1) rp[N_NODE] = prefix;
}

__global__ void fill_k(const int* __restrict__ ei, const int* __restrict__ rowptr,
                       int* __restrict__ cur, int* __restrict__ col, int E) {
    int i = blockIdx.x * blockDim.x + threadIdx.x;
    int st = gridDim.x * blockDim.x;
    for (; i < E; i += st) {
        int s = ei[i];
        int d = ei[E + i];
        int pos = rowptr[d] + atomicAdd(cur + d, 1);
        col[pos] = s;
    }
}

// ---------------- standalone CSR gather-mean: one warp per dst node ----------------
// agg[node,:] = inv[node] * sum_{j in row(node)} x[colidx[j],:]
__global__ void __launch_bounds__(256) gather_mean_k(
    const float* __restrict__ x, const int* __restrict__ rowptr,
    const int* __restrict__ colidx, const float* __restrict__ inv,
    float* __restrict__ agg, int n)
{
    int lane = threadIdx.x & 31;
    int w = (blockIdx.x * blockDim.x + threadIdx.x) >> 5;
    int nw = (gridDim.x * blockDim.x) >> 5;
    for (int node = w; node < n; node += nw) {
        int beg = __ldg(rowptr + node);
        int end = __ldg(rowptr + node + 1);
        float4 v = make_float4(0.f, 0.f, 0.f, 0.f);
        float4 v2 = make_float4(0.f, 0.f, 0.f, 0.f);
        int j = beg;
        for (; j + 1 < end; j += 2) {
            int s0 = __ldg(colidx + j);
            int s1 = __ldg(colidx + j + 1);
            float4 a = __ldg((const float4*)(x + (size_t)s0 * C) + lane);
            float4 b = __ldg((const float4*)(x + (size_t)s1 * C) + lane);
            v.x += a.x;  v.y += a.y;  v.z += a.z;  v.w += a.w;
            v2.x += b.x; v2.y += b.y; v2.z += b.z; v2.w += b.w;
        }
        if (j < end) {
            int s0 = __ldg(colidx + j);
            float4 a = __ldg((const float4*)(x + (size_t)s0 * C) + lane);
            v.x += a.x; v.y += a.y; v.z += a.z; v.w += a.w;
        }
        float sc = __ldg(inv + node);
        v.x = (v.x + v2.x) * sc;
        v.y = (v.y + v2.y) * sc;
        v.z = (v.z + v2.z) * sc;
        v.w = (v.w + v2.w) * sc;
        *((float4*)(agg + (size_t)node * C) + lane) = v;
    }
}

// ================ tf32 mma.sync GEMM + bias + LayerNorm + ReLU ================
// D[m,n] = sum_terms A_t[m,:] @ W_t[:,n], CTA tile 128x128, K=128.
// 8 warps in 2M x 4N; each warp 64x32 via m16n8k8.row.col.f32.tf32.tf32.f32.
// Fragment smem layouts padded: A ks-stride 1028 (2-way STS), B nt-stride 70 (2-way STS).

__device__ __forceinline__ uint32_t f2tf32(float x) {
    uint32_t o; asm("cvt.rna.tf32.f32 %0, %1;" : "=r"(o) : "f"(x)); return o;
}

#define MMA_TF32(d, a, b)                                                       \
    asm volatile("mma.sync.aligned.m16n8k8.row.col.f32.tf32.tf32.f32 "          \
                 "{%0,%1,%2,%3}, {%4,%5,%6,%7}, {%8,%9}, {%0,%1,%2,%3};"        \
                 : "+f"((d)[0]), "+f"((d)[1]), "+f"((d)[2]), "+f"((d)[3])       \
                 : "r"((a).x), "r"((a).y), "r"((a).z), "r"((a).w),              \
                   "r"((b).x), "r"((b).y))

// SMEM layout (bytes)
#define SM_A      0          // 16 ks x 1028 uint32 = 65792 B
#define SM_B      65792      // 16 ks x 16 nt x 70 uint32 = 71680 B
#define SM_PART   137472     // 128 rows x 4 warps x float2 = 4KB
#define SM_STAT   141568     // 128 x float2 (mu, rs) = 1KB
#define SM_BIAS   142592     // 128 f32
#define SM_LNW    143104
#define SM_LNB    143616
#define GEMM_SMEM 144128

#define GEMM_GRID 782        // ceil(100000 / 128)

// A uint32 idx = ks*1028 + mt*128 + (m&7)*16 + e*4 + slot,
//   slot = ((m>>3)&1) | (((k>>2)&1)<<1), ks=k>>3, mt=m>>4, e=k&3.
// B uint32 idx = (ks*16+nt)*70 + (n&7)*8 + (k&3)*2 + ((k>>2)&1).

__device__ __forceinline__ void stage_A(uint32_t* sA, const float* __restrict__ A,
                                        int nodeBase, int N, int t)
{
#pragma unroll 4
    for (int i = 0; i < 16; ++i) {
        int f = t + i * 256;              // 0..4095 float4 slots; m=f>>5, k4=f&31
        int m = f >> 5, k4 = f & 31;
        int node = nodeBase + m;
        float4 v = make_float4(0.f, 0.f, 0.f, 0.f);
        if (node < N) v = __ldg((const float4*)(A + (size_t)node * C) + k4);
        int ks = k4 >> 1;
        int mt = m >> 4;
        int slot = ((m >> 3) & 1) | ((k4 & 1) << 1);
        int base = ks * 1028 + mt * 128 + ((m & 7) << 4) + slot;
        sA[base + 0 * 4] = f2tf32(v.x);
        sA[base + 1 * 4] = f2tf32(v.y);
        sA[base + 2 * 4] = f2tf32(v.z);
        sA[base + 3 * 4] = f2tf32(v.w);
    }
}

// B = W [128k x 128n] row-major -> fragment order
__device__ __forceinline__ void stage_B(uint32_t* sB, const float* __restrict__ W, int t)
{
#pragma unroll 4
    for (int i = 0; i < 16; ++i) {
        int f = t + i * 256;              // k=f>>5 (warp-uniform), n4=f&31 (=lane)
        int k = f >> 5, n4 = f & 31;
        float4 w = __ldg((const float4*)W + f);
        int ks = k >> 3;
        int nt = n4 >> 1;
        int slot = (k >> 2) & 1;
        int n0_7 = (n4 & 1) << 2;
        int base = (ks * 16 + nt) * 70 + (k & 3) * 2 + slot;
        sB[base + (n0_7 + 0) * 8] = f2tf32(w.x);
        sB[base + (n0_7 + 1) * 8] = f2tf32(w.y);
        sB[base + (n0_7 + 2) * 8] = f2tf32(w.z);
        sB[base + (n0_7 + 3) * 8] = f2tf32(w.w);
    }
}

template <int NTERMS>
__global__ void __launch_bounds__(256) gemm_mma(
    const float* __restrict__ A0, const float* __restrict__ W0,
    const float* __restrict__ A1, const float* __restrict__ W1,
    const float* __restrict__ A2, const float* __restrict__ W2,
    const float* __restrict__ bias0, const float* __restrict__ bias1,
    const float* __restrict__ lnw, const float* __restrict__ lnb,
    float* __restrict__ out, int N)
{
    extern __shared__ char smem[];
    uint32_t* sA = (uint32_t*)(smem + SM_A);
    uint32_t* sB = (uint32_t*)(smem + SM_B);
    float2* sPart = (float2*)(smem + SM_PART);
    float2* sStat = (float2*)(smem + SM_STAT);
    float* sBias  = (float*)(smem + SM_BIAS);
    float* sLnw   = (float*)(smem + SM_LNW);
    float* sLnb   = (float*)(smem + SM_LNB);

    const int t = threadIdx.x;
    const int warp = t >> 5;
    const int lane = t & 31;
    const int wm = warp >> 2;     // 0..1  (M half)
    const int wn = warp & 3;      // 0..3  (N quarter)
    const int nodeBase = blockIdx.x * 128;

    if (t < 128) {
        float b = bias0 ? __ldg(bias0 + t) : 0.f;
        if (bias1) b += __ldg(bias1 + t);
        sBias[t] = b;
        sLnw[t] = __ldg(lnw + t);
        sLnb[t] = __ldg(lnb + t);
    }

    const float* As[3] = {A0, A1, A2};
    const float* Ws[3] = {W0, W1, W2};

    float acc[4][4][4];
#pragma unroll
    for (int a = 0; a < 4; ++a)
#pragma unroll
        for (int b = 0; b < 4; ++b)
#pragma unroll
            for (int c = 0; c < 4; ++c) acc[a][b][c] = 0.f;

    const uint4* sA4 = (const uint4*)sA;
    const uint2* sB2 = (const uint2*)sB;

#pragma unroll 1
    for (int term = 0; term < NTERMS; ++term) {
        if (term > 0) __syncthreads();    // all warps done reading previous tiles
        stage_A(sA, As[term], nodeBase, N, t);
        stage_B(sB, Ws[term], t);
        __syncthreads();

#pragma unroll 1
        for (int ks = 0; ks < 16; ++ks) {
            uint4 af[4];
            uint2 bf[4];
#pragma unroll
            for (int mt = 0; mt < 4; ++mt)
                af[mt] = sA4[ks * 257 + (wm * 4 + mt) * 32 + lane];
#pragma unroll
            for (int nt = 0; nt < 4; ++nt)
                bf[nt] = sB2[(ks * 16 + wn * 4 + nt) * 35 + lane];
#pragma unroll
            for (int mt = 0; mt < 4; ++mt)
#pragma unroll
                for (int nt = 0; nt < 4; ++nt)
                    MMA_TF32(acc[mt][nt], af[mt], bf[nt]);
        }
    }

    // ---------------- epilogue: bias + LayerNorm + ReLU ----------------
    // Thread owns rows (wm*4+mt)*16 + hi*8 + lane/4, cols (wn*4+nt)*8 + (lane&3)*2 + e.
#pragma unroll
    for (int mt = 0; mt < 4; ++mt) {
#pragma unroll
        for (int hi = 0; hi < 2; ++hi) {
            float s = 0.f, q = 0.f;
#pragma unroll
            for (int nt = 0; nt < 4; ++nt) {
#pragma unroll
                for (int e = 0; e < 2; ++e) {
                    int col = (wn * 4 + nt) * 8 + (lane & 3) * 2 + e;
                    float v = acc[mt][nt][hi * 2 + e] + sBias[col];
                    s += v; q += v * v;
                }
            }
            s += __shfl_xor_sync(0xffffffffu, s, 1);
            q += __shfl_xor_sync(0xffffffffu, q, 1);
            s += __shfl_xor_sync(0xffffffffu, s, 2);
            q += __shfl_xor_sync(0xffffffffu, q, 2);
            if ((lane & 3) == 0) {
                int row = (wm * 4 + mt) * 16 + hi * 8 + (lane >> 2);
                sPart[row * 4 + wn] = make_float2(s, q);
            }
        }
    }
    __syncthreads();
    if (t < 128) {
        float2 p0 = sPart[t * 4 + 0], p1 = sPart[t * 4 + 1];
        float2 p2 = sPart[t * 4 + 2], p3 = sPart[t * 4 + 3];
        float s = p0.x + p1.x + p2.x + p3.x;
        float q = p0.y + p1.y + p2.y + p3.y;
        float mu = s * (1.0f / C);
        float var = q * (1.0f / C) - mu * mu;
        sStat[t] = make_float2(mu, rsqrtf(var + 1e-5f));
    }
    __syncthreads();

#pragma unroll
    for (int mt = 0; mt < 4; ++mt) {
#pragma unroll
        for (int hi = 0; hi < 2; ++hi) {
            int row = (wm * 4 + mt) * 16 + hi * 8 + (lane >> 2);
            int node = nodeBase + row;
            if (node < N) {
                float2 st = sStat[row];
#pragma unroll
                for (int nt = 0; nt < 4; ++nt) {
                    int col = (wn * 4 + nt) * 8 + (lane & 3) * 2;
                    float v0 = acc[mt][nt][hi * 2 + 0] + sBias[col];
                    float v1 = acc[mt][nt][hi * 2 + 1] + sBias[col + 1];
                    float2 o;
                    o.x = fmaxf((v0 - st.x) * st.y * sLnw[col]     + sLnb[col],     0.f);
                    o.y = fmaxf((v1 - st.x) * st.y * sLnw[col + 1] + sLnb[col + 1], 0.f);
                    *(float2*)(out + (size_t)node * C + col) = o;
                }
            }
        }
    }
}

// ---------------- host launcher ----------------
extern "C" void kernel_launch(void* const* d_in, const int* in_sizes, int n_in,
                              void* d_out, int out_size)
{
    const float* x_user = (const float*)d_in[0];
    const float* x_item = (const float*)d_in[1];
    const int*   ei_ui  = (const int*)d_in[2];
    const int*   ei_iu  = (const int*)d_in[3];
    const int*   ei_uu  = (const int*)d_in[4];
    const float* Wl     = (const float*)d_in[5];
    const float* bl     = (const float*)d_in[6];
    const float* Wr     = (const float*)d_in[7];
    const float* ln_w   = (const float*)d_in[8];
    const float* ln_b   = (const float*)d_in[9];
    float* out = (float*)d_out;

    void *pxu_, *pxi_, *pagg_, *pcnt_, *pinv_, *pws_, *prp_, *pci_, *pcur_;
    cudaGetSymbolAddress(&pxu_, g_xu);
    cudaGetSymbolAddress(&pxi_, g_xi);
    cudaGetSymbolAddress(&pagg_, g_agg);
    cudaGetSymbolAddress(&pcnt_, g_cnt);
    cudaGetSymbolAddress(&pinv_, g_inv);
    cudaGetSymbolAddress(&pws_, g_wsum);
    cudaGetSymbolAddress(&prp_, g_rowptr);
    cudaGetSymbolAddress(&pci_, g_colidx);
    cudaGetSymbolAddress(&pcur_, g_cur);
    float* pxu  = (float*)pxu_;
    float* pxi  = (float*)pxi_;
    float* pagg = (float*)pagg_;
    int*   pcnt = (int*)pcnt_;
    float* pinv = (float*)pinv_;
    float* pws  = (float*)pws_;
    int*   prp  = (int*)prp_;
    int*   pci  = (int*)pci_;
    int*   pcur = (int*)pcur_;

    cudaFuncSetAttribute((const void*)gemm_mma<2>,
                         cudaFuncAttributeMaxDynamicSharedMemorySize, GEMM_SMEM);
    cudaFuncSetAttribute((const void*)gemm_mma<3>,
                         cudaFuncAttributeMaxDynamicSharedMemorySize, GEMM_SMEM);

    // ---- CSR build (edges identical across layers: once per call) ----
    zero_k<<<128, 256>>>((float4*)pcnt, (long)(3 * N_NODE) / 4);
    zero_k<<<128, 256>>>((float4*)pcur, (long)(3 * N_NODE) / 4);
    count_k<<<2048, 256>>>(ei_ui + NEDGE, pcnt + 0 * N_NODE, NEDGE);
    count_k<<<2048, 256>>>(ei_iu + NEDGE, pcnt + 1 * N_NODE, NEDGE);
    count_k<<<2048, 256>>>(ei_uu + NEDGE, pcnt + 2 * N_NODE, NEDGE);
    inv_k<<<(3 * N_NODE + 255) / 256, 256>>>(pcnt, pinv, 3 * N_NODE);
    scan_k<<<3, SCAN_T>>>(pcnt, prp);
    fill_k<<<2048, 256>>>(ei_ui, prp + 0 * (N_NODE + 1), pcur + 0 * N_NODE,
                          pci + 0 * NEDGE, NEDGE);
    fill_k<<<2048, 256>>>(ei_iu, prp + 1 * (N_NODE + 1), pcur + 1 * N_NODE,
                          pci + 1 * NEDGE, NEDGE);
    fill_k<<<2048, 256>>>(ei_uu, prp + 2 * (N_NODE + 1), pcur + 2 * N_NODE,
                          pci + 2 * NEDGE, NEDGE);

    // Wsum[l] = Wr[l,1] + Wr[l,2]  (fold the two xu @ Wr terms into one GEMM term)
    for (int l = 0; l < 2; ++l)
        addW_k<<<(CC + 255) / 256, 256>>>(Wr + (size_t)(l * 3 + 1) * CC,
                                          Wr + (size_t)(l * 3 + 2) * CC,
                                          pws + (size_t)l * CC, CC);

    const int GATHER_BLOCKS = 6144;   // 49152 warps, grid-stride over 100k nodes

    for (int l = 0; l < 2; ++l) {
        const float* xu_src = (l == 0) ? x_user : pxu;
        const float* xi_src = (l == 0) ? x_item : pxi;
        float* outu = (l == 0) ? pxu : out;
        float* outi = (l == 0) ? pxi : out + NC;

        // gather means (standalone, latency hidden by ~50k concurrent warps)
        gather_mean_k<<<GATHER_BLOCKS, 256>>>(
            xu_src, prp + 0 * (N_NODE + 1), pci + 0 * NEDGE,
            pinv + 0 * N_NODE, pagg + 0 * NC, N_NODE);
        gather_mean_k<<<GATHER_BLOCKS, 256>>>(
            xi_src, prp + 1 * (N_NODE + 1), pci + 1 * NEDGE,
            pinv + 1 * N_NODE, pagg + 1 * NC, N_NODE);
        gather_mean_k<<<GATHER_BLOCKS, 256>>>(
            xu_src, prp + 2 * (N_NODE + 1), pci + 2 * NEDGE,
            pinv + 2 * N_NODE, pagg + 2 * NC, N_NODE);

        // item: mean_ui @ Wl[l,0] + bl[l,0] + xi @ Wr[l,0] -> LN(item) -> ReLU
        gemm_mma<2><<<GEMM_GRID, 256, GEMM_SMEM>>>(
            pagg + 0 * NC, Wl + (size_t)(l * 3 + 0) * CC,
            xi_src,        Wr + (size_t)(l * 3 + 0) * CC,
            nullptr,       nullptr,
            bl + (size_t)(l * 3 + 0) * C, nullptr,
            ln_w + (size_t)(l * 2 + 1) * C, ln_b + (size_t)(l * 2 + 1) * C,
            outi, N_NODE);

        // user: mean_iu@Wl[l,1] + mean_uu@Wl[l,2] + xu@(Wr[l,1]+Wr[l,2]) + biases
        gemm_mma<3><<<GEMM_GRID, 256, GEMM_SMEM>>>(
            pagg + 1 * NC, Wl + (size_t)(l * 3 + 1) * CC,
            pagg + 2 * NC, Wl + (size_t)(l * 3 + 2) * CC,
            xu_src,        pws + (size_t)l * CC,
            bl + (size_t)(l * 3 + 1) * C, bl + (size_t)(l * 3 + 2) * C,
            ln_w + (size_t)(l * 2 + 0) * C, ln_b + (size_t)(l * 2 + 0) * C,
            outu, N_NODE);
    }
}

// round 11
// speedup vs baseline: 2.6909x; 1.6362x over previous
#include <cuda_runtime.h>
#include <cstdint>

#define N_NODE 100000        // N_USER == N_ITEM == 100000
#define NEDGE  1000000
#define C      128
#define CC     (C * C)
#define NC     ((size_t)N_NODE * C)

// ---------------- device scratch (allowed: __device__ globals) ----------------
__device__ __align__(16) float g_xu[NC];            // user features after layer 0
__device__ __align__(16) float g_xi[NC];            // item features after layer 0
__device__ __align__(16) float g_agg[3][NC];        // gathered means per edge type
__device__ __align__(16) int   g_cnt[3 * N_NODE];
__device__ __align__(16) float g_wsum[2 * CC];      // Wr[l,1]+Wr[l,2] per layer
__device__ __align__(16) int   g_rowptr[3 * (N_NODE + 1)];
__device__ __align__(16) int   g_colidx[3 * NEDGE];
__device__ __align__(16) int   g_cur[3 * N_NODE];

// ---------------- utility kernels ----------------
__global__ void zero2_k(float4* __restrict__ a, long na4,
                        float4* __restrict__ b, long nb4) {
    long i = (long)blockIdx.x * blockDim.x + threadIdx.x;
    long st = (long)gridDim.x * blockDim.x;
    float4 z = make_float4(0.f, 0.f, 0.f, 0.f);
    for (long j = i; j < na4; j += st) a[j] = z;
    for (long j = i; j < nb4; j += st) b[j] = z;
}

// all 3 edge types in one launch: blockIdx.y selects type
__global__ void count3_k(const int* __restrict__ d0, const int* __restrict__ d1,
                         const int* __restrict__ d2, int* __restrict__ cnt, int E) {
    const int* dst = (blockIdx.y == 0) ? d0 : (blockIdx.y == 1) ? d1 : d2;
    int* c = cnt + blockIdx.y * N_NODE;
    int i = blockIdx.x * blockDim.x + threadIdx.x;
    int st = gridDim.x * blockDim.x;
    for (; i < E; i += st) atomicAdd(c + dst[i], 1);
}

__global__ void fill3_k(const int* __restrict__ e0, const int* __restrict__ e1,
                        const int* __restrict__ e2, const int* __restrict__ rowptr,
                        int* __restrict__ cur, int* __restrict__ col, int E) {
    const int* ei = (blockIdx.y == 0) ? e0 : (blockIdx.y == 1) ? e1 : e2;
    const int* rp = rowptr + blockIdx.y * (N_NODE + 1);
    int* cu = cur + blockIdx.y * N_NODE;
    int* co = col + blockIdx.y * NEDGE;
    int i = blockIdx.x * blockDim.x + threadIdx.x;
    int st = gridDim.x * blockDim.x;
    for (; i < E; i += st) {
        int s = ei[i];
        int d = ei[E + i];
        int pos = rp[d] + atomicAdd(cu + d, 1);
        co[pos] = s;
    }
}

__global__ void addW_k(const float* __restrict__ a, const float* __restrict__ b,
                       float* __restrict__ o, int n) {
    int i = blockIdx.x * blockDim.x + threadIdx.x;
    if (i < n) o[i] = a[i] + b[i];
}

// exclusive scan of one edge type's counts -> rowptr. One block per type.
#define SCAN_T 1024
__global__ void __launch_bounds__(SCAN_T) scan_k(const int* __restrict__ cnt,
                                                 int* __restrict__ rowptr) {
    int type = blockIdx.x;
    const int* c = cnt + type * N_NODE;
    int* rp = rowptr + type * (N_NODE + 1);
    __shared__ int part[SCAN_T];
    int t = threadIdx.x;
    const int chunk = (N_NODE + SCAN_T - 1) / SCAN_T;   // 98
    int beg = t * chunk;
    int end = beg + chunk; if (end > N_NODE) end = N_NODE;
    int s = 0;
    for (int i = beg; i < end; ++i) s += c[i];
    part[t] = s;
    __syncthreads();
    for (int off = 1; off < SCAN_T; off <<= 1) {
        int v = (t >= off) ? part[t - off] : 0;
        __syncthreads();
        part[t] += v;
        __syncthreads();
    }
    int prefix = (t == 0) ? 0 : part[t - 1];
    for (int i = beg; i < end; ++i) {
        rp[i] = prefix;
        prefix += c[i];
    }
    if (t == SCAN_T - 1) rp[N_NODE] = prefix;
}

// ---------------- standalone CSR gather-mean: one warp per dst node ----------------
// agg[node,:] = (1/max(deg,1)) * sum_{j in row(node)} x[colidx[j],:], deg from rowptr.
__global__ void __launch_bounds__(256) gather_mean_k(
    const float* __restrict__ x, const int* __restrict__ rowptr,
    const int* __restrict__ colidx, float* __restrict__ agg, int n)
{
    int lane = threadIdx.x & 31;
    int w = (blockIdx.x * blockDim.x + threadIdx.x) >> 5;
    int nw = (gridDim.x * blockDim.x) >> 5;
    for (int node = w; node < n; node += nw) {
        int beg = __ldg(rowptr + node);
        int end = __ldg(rowptr + node + 1);
        float4 v0 = make_float4(0.f, 0.f, 0.f, 0.f);
        float4 v1 = v0, v2 = v0, v3 = v0;
        int j = beg;
        for (; j + 3 < end; j += 4) {
            int s0 = __ldg(colidx + j);
            int s1 = __ldg(colidx + j + 1);
            int s2 = __ldg(colidx + j + 2);
            int s3 = __ldg(colidx + j + 3);
            float4 a = __ldg((const float4*)(x + (size_t)s0 * C) + lane);
            float4 b = __ldg((const float4*)(x + (size_t)s1 * C) + lane);
            float4 c = __ldg((const float4*)(x + (size_t)s2 * C) + lane);
            float4 d = __ldg((const float4*)(x + (size_t)s3 * C) + lane);
            v0.x += a.x; v0.y += a.y; v0.z += a.z; v0.w += a.w;
            v1.x += b.x; v1.y += b.y; v1.z += b.z; v1.w += b.w;
            v2.x += c.x; v2.y += c.y; v2.z += c.z; v2.w += c.w;
            v3.x += d.x; v3.y += d.y; v3.z += d.z; v3.w += d.w;
        }
        for (; j < end; ++j) {
            int s0 = __ldg(colidx + j);
            float4 a = __ldg((const float4*)(x + (size_t)s0 * C) + lane);
            v0.x += a.x; v0.y += a.y; v0.z += a.z; v0.w += a.w;
        }
        int cdeg = end - beg;
        float sc = 1.0f / (float)(cdeg > 1 ? cdeg : 1);
        v0.x = (v0.x + v1.x + v2.x + v3.x) * sc;
        v0.y = (v0.y + v1.y + v2.y + v3.y) * sc;
        v0.z = (v0.z + v1.z + v2.z + v3.z) * sc;
        v0.w = (v0.w + v1.w + v2.w + v3.w) * sc;
        *((float4*)(agg + (size_t)node * C) + lane) = v0;
    }
}

// ================ tf32 mma.sync GEMM + bias + LayerNorm + ReLU ================
// Software-pipelined: next term's A/B tiles prefetched to registers during MMA.
// CTA tile 128x128, K=128; 8 warps 2M x 4N; warp 64x32 via m16n8k8 tf32.
// Padded fragment layouts: A ks-stride 1028, B nt-stride 70 (2-way STS).

__device__ __forceinline__ uint32_t f2tf32(float x) {
    uint32_t o; asm("cvt.rna.tf32.f32 %0, %1;" : "=r"(o) : "f"(x)); return o;
}

#define MMA_TF32(d, a, b)                                                       \
    asm volatile("mma.sync.aligned.m16n8k8.row.col.f32.tf32.tf32.f32 "          \
                 "{%0,%1,%2,%3}, {%4,%5,%6,%7}, {%8,%9}, {%0,%1,%2,%3};"        \
                 : "+f"((d)[0]), "+f"((d)[1]), "+f"((d)[2]), "+f"((d)[3])       \
                 : "r"((a).x), "r"((a).y), "r"((a).z), "r"((a).w),              \
                   "r"((b).x), "r"((b).y))

// SMEM layout (bytes)
#define SM_A      0          // 16 ks x 1028 uint32 = 65792 B
#define SM_B      65792      // 16 ks x 16 nt x 70 uint32 = 71680 B
#define SM_PART   137472     // 128 rows x 4 warps x float2 = 4KB
#define SM_STAT   141568     // 128 x float2 (mu, rs) = 1KB
#define SM_BIAS   142592     // 128 f32
#define SM_LNW    143104
#define SM_LNB    143616
#define GEMM_SMEM 144128

#define GEMM_GRID 782        // ceil(100000 / 128)

// A uint32 idx = ks*1028 + mt*128 + (m&7)*16 + e*4 + slot,
//   slot = ((m>>3)&1) | (((k>>2)&1)<<1), ks=k>>3, mt=m>>4, e=k&3.
// B uint32 idx = (ks*16+nt)*70 + (n&7)*8 + (k&3)*2 + ((k>>2)&1).

__device__ __forceinline__ void ldg_A(float4* pa, const float* __restrict__ A,
                                      int nodeBase, int N, int t)
{
#pragma unroll
    for (int i = 0; i < 16; ++i) {
        int f = t + i * 256;
        int m = f >> 5, k4 = f & 31;
        int node = nodeBase + m;
        pa[i] = (node < N) ? __ldg((const float4*)(A + (size_t)node * C) + k4)
                           : make_float4(0.f, 0.f, 0.f, 0.f);
    }
}

__device__ __forceinline__ void sts_A(uint32_t* sA, const float4* pa, int t)
{
#pragma unroll
    for (int i = 0; i < 16; ++i) {
        int f = t + i * 256;
        int m = f >> 5, k4 = f & 31;
        int ks = k4 >> 1;
        int mt = m >> 4;
        int slot = ((m >> 3) & 1) | ((k4 & 1) << 1);
        int base = ks * 1028 + mt * 128 + ((m & 7) << 4) + slot;
        sA[base + 0 * 4] = f2tf32(pa[i].x);
        sA[base + 1 * 4] = f2tf32(pa[i].y);
        sA[base + 2 * 4] = f2tf32(pa[i].z);
        sA[base + 3 * 4] = f2tf32(pa[i].w);
    }
}

__device__ __forceinline__ void ldg_B(float4* pb, const float* __restrict__ W, int t)
{
#pragma unroll
    for (int i = 0; i < 16; ++i) pb[i] = __ldg((const float4*)W + t + i * 256);
}

__device__ __forceinline__ void sts_B(uint32_t* sB, const float4* pb, int t)
{
#pragma unroll
    for (int i = 0; i < 16; ++i) {
        int f = t + i * 256;
        int k = f >> 5, n4 = f & 31;
        int ks = k >> 3;
        int nt = n4 >> 1;
        int slot = (k >> 2) & 1;
        int n0_7 = (n4 & 1) << 2;
        int base = (ks * 16 + nt) * 70 + (k & 3) * 2 + slot;
        sB[base + (n0_7 + 0) * 8] = f2tf32(pb[i].x);
        sB[base + (n0_7 + 1) * 8] = f2tf32(pb[i].y);
        sB[base + (n0_7 + 2) * 8] = f2tf32(pb[i].z);
        sB[base + (n0_7 + 3) * 8] = f2tf32(pb[i].w);
    }
}

template <int NTERMS>
__global__ void __launch_bounds__(256) gemm_mma(
    const float* __restrict__ A0, const float* __restrict__ W0,
    const float* __restrict__ A1, const float* __restrict__ W1,
    const float* __restrict__ A2, const float* __restrict__ W2,
    const float* __restrict__ bias0, const float* __restrict__ bias1,
    const float* __restrict__ lnw, const float* __restrict__ lnb,
    float* __restrict__ out, int N)
{
    extern __shared__ char smem[];
    uint32_t* sA = (uint32_t*)(smem + SM_A);
    uint32_t* sB = (uint32_t*)(smem + SM_B);
    float2* sPart = (float2*)(smem + SM_PART);
    float2* sStat = (float2*)(smem + SM_STAT);
    float* sBias  = (float*)(smem + SM_BIAS);
    float* sLnw   = (float*)(smem + SM_LNW);
    float* sLnb   = (float*)(smem + SM_LNB);

    const int t = threadIdx.x;
    const int warp = t >> 5;
    const int lane = t & 31;
    const int wm = warp >> 2;     // 0..1  (M half)
    const int wn = warp & 3;      // 0..3  (N quarter)
    const int nodeBase = blockIdx.x * 128;

    if (t < 128) {
        float b = bias0 ? __ldg(bias0 + t) : 0.f;
        if (bias1) b += __ldg(bias1 + t);
        sBias[t] = b;
        sLnw[t] = __ldg(lnw + t);
        sLnb[t] = __ldg(lnb + t);
    }

    const float* As[3] = {A0, A1, A2};
    const float* Ws[3] = {W0, W1, W2};

    float acc[4][4][4];
#pragma unroll
    for (int a = 0; a < 4; ++a)
#pragma unroll
        for (int b = 0; b < 4; ++b)
#pragma unroll
            for (int c = 0; c < 4; ++c) acc[a][b][c] = 0.f;

    const uint4* sA4 = (const uint4*)sA;
    const uint2* sB2 = (const uint2*)sB;

    float4 pa[16], pb[16];
    ldg_A(pa, As[0], nodeBase, N, t);
    ldg_B(pb, Ws[0], t);

#pragma unroll 1
    for (int term = 0; term < NTERMS; ++term) {
        if (term > 0) __syncthreads();    // all warps done reading previous tiles
        sts_A(sA, pa, t);
        sts_B(sB, pb, t);
        __syncthreads();
        if (term + 1 < NTERMS) {          // prefetch next term behind the MMAs
            ldg_A(pa, As[term + 1], nodeBase, N, t);
            ldg_B(pb, Ws[term + 1], t);
        }

#pragma unroll 1
        for (int ks = 0; ks < 16; ++ks) {
            uint4 af[4];
            uint2 bf[4];
#pragma unroll
            for (int mt = 0; mt < 4; ++mt)
                af[mt] = sA4[ks * 257 + (wm * 4 + mt) * 32 + lane];
#pragma unroll
            for (int nt = 0; nt < 4; ++nt)
                bf[nt] = sB2[(ks * 16 + wn * 4 + nt) * 35 + lane];
#pragma unroll
            for (int mt = 0; mt < 4; ++mt)
#pragma unroll
                for (int nt = 0; nt < 4; ++nt)
                    MMA_TF32(acc[mt][nt], af[mt], bf[nt]);
        }
    }

    // ---------------- epilogue: bias + LayerNorm + ReLU ----------------
#pragma unroll
    for (int mt = 0; mt < 4; ++mt) {
#pragma unroll
        for (int hi = 0; hi < 2; ++hi) {
            float s = 0.f, q = 0.f;
#pragma unroll
            for (int nt = 0; nt < 4; ++nt) {
#pragma unroll
                for (int e = 0; e < 2; ++e) {
                    int col = (wn * 4 + nt) * 8 + (lane & 3) * 2 + e;
                    float v = acc[mt][nt][hi * 2 + e] + sBias[col];
                    s += v; q += v * v;
                }
            }
            s += __shfl_xor_sync(0xffffffffu, s, 1);
            q += __shfl_xor_sync(0xffffffffu, q, 1);
            s += __shfl_xor_sync(0xffffffffu, s, 2);
            q += __shfl_xor_sync(0xffffffffu, q, 2);
            if ((lane & 3) == 0) {
                int row = (wm * 4 + mt) * 16 + hi * 8 + (lane >> 2);
                sPart[row * 4 + wn] = make_float2(s, q);
            }
        }
    }
    __syncthreads();
    if (t < 128) {
        float2 p0 = sPart[t * 4 + 0], p1 = sPart[t * 4 + 1];
        float2 p2 = sPart[t * 4 + 2], p3 = sPart[t * 4 + 3];
        float s = p0.x + p1.x + p2.x + p3.x;
        float q = p0.y + p1.y + p2.y + p3.y;
        float mu = s * (1.0f / C);
        float var = q * (1.0f / C) - mu * mu;
        sStat[t] = make_float2(mu, rsqrtf(var + 1e-5f));
    }
    __syncthreads();

#pragma unroll
    for (int mt = 0; mt < 4; ++mt) {
#pragma unroll
        for (int hi = 0; hi < 2; ++hi) {
            int row = (wm * 4 + mt) * 16 + hi * 8 + (lane >> 2);
            int node = nodeBase + row;
            if (node < N) {
                float2 st = sStat[row];
#pragma unroll
                for (int nt = 0; nt < 4; ++nt) {
                    int col = (wn * 4 + nt) * 8 + (lane & 3) * 2;
                    float v0 = acc[mt][nt][hi * 2 + 0] + sBias[col];
                    float v1 = acc[mt][nt][hi * 2 + 1] + sBias[col + 1];
                    float2 o;
                    o.x = fmaxf((v0 - st.x) * st.y * sLnw[col]     + sLnb[col],     0.f);
                    o.y = fmaxf((v1 - st.x) * st.y * sLnw[col + 1] + sLnb[col + 1], 0.f);
                    *(float2*)(out + (size_t)node * C + col) = o;
                }
            }
        }
    }
}

// ---------------- host launcher ----------------
extern "C" void kernel_launch(void* const* d_in, const int* in_sizes, int n_in,
                              void* d_out, int out_size)
{
    const float* x_user = (const float*)d_in[0];
    const float* x_item = (const float*)d_in[1];
    const int*   ei_ui  = (const int*)d_in[2];
    const int*   ei_iu  = (const int*)d_in[3];
    const int*   ei_uu  = (const int*)d_in[4];
    const float* Wl     = (const float*)d_in[5];
    const float* bl     = (const float*)d_in[6];
    const float* Wr     = (const float*)d_in[7];
    const float* ln_w   = (const float*)d_in[8];
    const float* ln_b   = (const float*)d_in[9];
    float* out = (float*)d_out;

    void *pxu_, *pxi_, *pagg_, *pcnt_, *pws_, *prp_, *pci_, *pcur_;
    cudaGetSymbolAddress(&pxu_, g_xu);
    cudaGetSymbolAddress(&pxi_, g_xi);
    cudaGetSymbolAddress(&pagg_, g_agg);
    cudaGetSymbolAddress(&pcnt_, g_cnt);
    cudaGetSymbolAddress(&pws_, g_wsum);
    cudaGetSymbolAddress(&prp_, g_rowptr);
    cudaGetSymbolAddress(&pci_, g_colidx);
    cudaGetSymbolAddress(&pcur_, g_cur);
    float* pxu  = (float*)pxu_;
    float* pxi  = (float*)pxi_;
    float* pagg = (float*)pagg_;
    int*   pcnt = (int*)pcnt_;
    float* pws  = (float*)pws_;
    int*   prp  = (int*)prp_;
    int*   pci  = (int*)pci_;
    int*   pcur = (int*)pcur_;

    cudaFuncSetAttribute((const void*)gemm_mma<2>,
                         cudaFuncAttributeMaxDynamicSharedMemorySize, GEMM_SMEM);
    cudaFuncSetAttribute((const void*)gemm_mma<3>,
                         cudaFuncAttributeMaxDynamicSharedMemorySize, GEMM_SMEM);

    const int GATHER_BLOCKS = 6144;

    // ---- CSR build: 4 launches (launch slots 1-4) ----
    zero2_k<<<128, 256>>>((float4*)pcnt, (long)(3 * N_NODE) / 4,
                          (float4*)pcur, (long)(3 * N_NODE) / 4);
    count3_k<<<dim3(1024, 3), 256>>>(ei_ui + NEDGE, ei_iu + NEDGE, ei_uu + NEDGE,
                                     pcnt, NEDGE);
    scan_k<<<3, SCAN_T>>>(pcnt, prp);
    fill3_k<<<dim3(1024, 3), 256>>>(ei_ui, ei_iu, ei_uu, prp, pcur, pci, NEDGE);

    bool first = true;
    for (int l = 0; l < 2; ++l) {
        const float* xu_src = (l == 0) ? x_user : pxu;
        const float* xi_src = (l == 0) ? x_item : pxi;
        float* outu = (l == 0) ? pxu : out;
        float* outi = (l == 0) ? pxi : out + NC;

        // slot 5 (l=0): gather type 0 (user->item)
        gather_mean_k<<<GATHER_BLOCKS, 256>>>(
            xu_src, prp + 0 * (N_NODE + 1), pci + 0 * NEDGE, pagg + 0 * NC, N_NODE);

        // slot 6 (l=0): item GEMM  <-- ncu -s 5 -c 1 profiles THIS
        gemm_mma<2><<<GEMM_GRID, 256, GEMM_SMEM>>>(
            pagg + 0 * NC, Wl + (size_t)(l * 3 + 0) * CC,
            xi_src,        Wr + (size_t)(l * 3 + 0) * CC,
            nullptr,       nullptr,
            bl + (size_t)(l * 3 + 0) * C, nullptr,
            ln_w + (size_t)(l * 2 + 1) * C, ln_b + (size_t)(l * 2 + 1) * C,
            outi, N_NODE);

        if (first) {   // Wsum needed only before gemm<3>; keep slots 5-6 clean
            for (int ll = 0; ll < 2; ++ll)
                addW_k<<<(CC + 255) / 256, 256>>>(Wr + (size_t)(ll * 3 + 1) * CC,
                                                  Wr + (size_t)(ll * 3 + 2) * CC,
                                                  pws + (size_t)ll * CC, CC);
            first = false;
        }

        gather_mean_k<<<GATHER_BLOCKS, 256>>>(
            xi_src, prp + 1 * (N_NODE + 1), pci + 1 * NEDGE, pagg + 1 * NC, N_NODE);
        gather_mean_k<<<GATHER_BLOCKS, 256>>>(
            xu_src, prp + 2 * (N_NODE + 1), pci + 2 * NEDGE, pagg + 2 * NC, N_NODE);

        // user: mean_iu@Wl[l,1] + mean_uu@Wl[l,2] + xu@(Wr[l,1]+Wr[l,2]) + biases
        gemm_mma<3><<<GEMM_GRID, 256, GEMM_SMEM>>>(
            pagg + 1 * NC, Wl + (size_t)(l * 3 + 1) * CC,
            pagg + 2 * NC, Wl + (size_t)(l * 3 + 2) * CC,
            xu_src,        pws + (size_t)l * CC,
            bl + (size_t)(l * 3 + 1) * C, bl + (size_t)(l * 3 + 2) * C,
            ln_w + (size_t)(l * 2 + 0) * C, ln_b + (size_t)(l * 2 + 0) * C,
            outu, N_NODE);
    }
}

// round 13
// speedup vs baseline: 2.7994x; 1.0403x over previous
#include <cuda_runtime.h>
#include <cuda_fp16.h>
#include <cstdint>

#define N_NODE 100000        // N_USER == N_ITEM == 100000
#define NEDGE  1000000
#define C      128
#define CC     (C * C)
#define NC     ((size_t)N_NODE * C)

// ---------------- device scratch (allowed: __device__ globals) ----------------
__device__ __align__(16) __half g_hu[NC];           // fp16 copy of x_user
__device__ __align__(16) __half g_hi[NC];           // fp16 copy of x_item
__device__ __align__(16) __half g_hxu[NC];          // layer-0 user output (fp16)
__device__ __align__(16) __half g_hxi[NC];          // layer-0 item output (fp16)
__device__ __align__(16) __half g_hagg[3][NC];      // gathered means (fp16)
__device__ __align__(16) int    g_cnt[3 * N_NODE];
__device__ __align__(16) float  g_wsum[2 * CC];     // Wr[l,1]+Wr[l,2] per layer
__device__ __align__(16) int    g_rowptr[3 * (N_NODE + 1)];
__device__ __align__(16) int    g_colidx[3 * NEDGE];
__device__ __align__(16) int    g_cur[3 * N_NODE];

// ---------------- utility kernels ----------------
__global__ void zero2_k(float4* __restrict__ a, long na4,
                        float4* __restrict__ b, long nb4) {
    long i = (long)blockIdx.x * blockDim.x + threadIdx.x;
    long st = (long)gridDim.x * blockDim.x;
    float4 z = make_float4(0.f, 0.f, 0.f, 0.f);
    for (long j = i; j < na4; j += st) a[j] = z;
    for (long j = i; j < nb4; j += st) b[j] = z;
}

// fp32 -> fp16 copies of both feature matrices
__global__ void cvt2h_k(const float4* __restrict__ xu, const float4* __restrict__ xi,
                        uint2* __restrict__ hu, uint2* __restrict__ hi, long n4) {
    long i = (long)blockIdx.x * blockDim.x + threadIdx.x;
    long st = (long)gridDim.x * blockDim.x;
    for (long j = i; j < n4; j += st) {
        float4 a = xu[j];
        uint2 w;
        *(__half2*)&w.x = __floats2half2_rn(a.x, a.y);
        *(__half2*)&w.y = __floats2half2_rn(a.z, a.w);
        hu[j] = w;
        float4 b = xi[j];
        *(__half2*)&w.x = __floats2half2_rn(b.x, b.y);
        *(__half2*)&w.y = __floats2half2_rn(b.z, b.w);
        hi[j] = w;
    }
}

// all 3 edge types in one launch: blockIdx.y selects type
__global__ void count3_k(const int* __restrict__ d0, const int* __restrict__ d1,
                         const int* __restrict__ d2, int* __restrict__ cnt, int E) {
    const int* dst = (blockIdx.y == 0) ? d0 : (blockIdx.y == 1) ? d1 : d2;
    int* c = cnt + blockIdx.y * N_NODE;
    int i = blockIdx.x * blockDim.x + threadIdx.x;
    int st = gridDim.x * blockDim.x;
    for (; i < E; i += st) atomicAdd(c + dst[i], 1);
}

__global__ void fill3_k(const int* __restrict__ e0, const int* __restrict__ e1,
                        const int* __restrict__ e2, const int* __restrict__ rowptr,
                        int* __restrict__ cur, int* __restrict__ col, int E) {
    const int* ei = (blockIdx.y == 0) ? e0 : (blockIdx.y == 1) ? e1 : e2;
    const int* rp = rowptr + blockIdx.y * (N_NODE + 1);
    int* cu = cur + blockIdx.y * N_NODE;
    int* co = col + blockIdx.y * NEDGE;
    int i = blockIdx.x * blockDim.x + threadIdx.x;
    int st = gridDim.x * blockDim.x;
    for (; i < E; i += st) {
        int s = ei[i];
        int d = ei[E + i];
        int pos = rp[d] + atomicAdd(cu + d, 1);
        co[pos] = s;
    }
}

__global__ void addW_k(const float* __restrict__ a, const float* __restrict__ b,
                       float* __restrict__ o, int n) {
    int i = blockIdx.x * blockDim.x + threadIdx.x;
    if (i < n) o[i] = a[i] + b[i];
}

// exclusive scan of one edge type's counts -> rowptr. One block per type.
#define SCAN_T 1024
__global__ void __launch_bounds__(SCAN_T) scan_k(const int* __restrict__ cnt,
                                                 int* __restrict__ rowptr) {
    int type = blockIdx.x;
    const int* c = cnt + type * N_NODE;
    int* rp = rowptr + type * (N_NODE + 1);
    __shared__ int part[SCAN_T];
    int t = threadIdx.x;
    const int chunk = (N_NODE + SCAN_T - 1) / SCAN_T;   // 98
    int beg = t * chunk;
    int end = beg + chunk; if (end > N_NODE) end = N_NODE;
    int s = 0;
    for (int i = beg; i < end; ++i) s += c[i];
    part[t] = s;
    __syncthreads();
    for (int off = 1; off < SCAN_T; off <<= 1) {
        int v = (t >= off) ? part[t - off] : 0;
        __syncthreads();
        part[t] += v;
        __syncthreads();
    }
    int prefix = (t == 0) ? 0 : part[t - 1];
    for (int i = beg; i < end; ++i) {
        rp[i] = prefix;
        prefix += c[i];
    }
    if (t == SCAN_T - 1) rp[N_NODE] = prefix;
}

// ---------------- CSR gather-mean (fp16 in / fp16 out), 3 types per launch ----------
// One warp per dst node; lane owns 4 feature columns (uint2 = 4 halfs per row).
__global__ void __launch_bounds__(256) gather3h_k(
    const __half* __restrict__ x0, const __half* __restrict__ x1,
    const __half* __restrict__ x2,
    const int* __restrict__ rowptr, const int* __restrict__ colidx,
    __half* __restrict__ agg, int n)
{
    int type = blockIdx.y;
    const __half* x = (type == 0) ? x0 : (type == 1) ? x1 : x2;
    const int* rp = rowptr + type * (N_NODE + 1);
    const int* ci = colidx + type * NEDGE;
    __half* out = agg + (size_t)type * NC;

    int lane = threadIdx.x & 31;
    int w = (blockIdx.x * blockDim.x + threadIdx.x) >> 5;
    int nw = (gridDim.x * blockDim.x) >> 5;
    for (int node = w; node < n; node += nw) {
        int beg = __ldg(rp + node);
        int end = __ldg(rp + node + 1);
        float4 v0 = make_float4(0.f, 0.f, 0.f, 0.f);
        float4 v1 = v0, v2 = v0, v3 = v0;
        int j = beg;
        for (; j + 3 < end; j += 4) {
            int s0 = __ldg(ci + j);
            int s1 = __ldg(ci + j + 1);
            int s2 = __ldg(ci + j + 2);
            int s3 = __ldg(ci + j + 3);
            uint2 a = __ldg((const uint2*)(x + (size_t)s0 * C) + lane);
            uint2 b = __ldg((const uint2*)(x + (size_t)s1 * C) + lane);
            uint2 c = __ldg((const uint2*)(x + (size_t)s2 * C) + lane);
            uint2 d = __ldg((const uint2*)(x + (size_t)s3 * C) + lane);
            float2 f;
            f = __half22float2(*(__half2*)&a.x); v0.x += f.x; v0.y += f.y;
            f = __half22float2(*(__half2*)&a.y); v0.z += f.x; v0.w += f.y;
            f = __half22float2(*(__half2*)&b.x); v1.x += f.x; v1.y += f.y;
            f = __half22float2(*(__half2*)&b.y); v1.z += f.x; v1.w += f.y;
            f = __half22float2(*(__half2*)&c.x); v2.x += f.x; v2.y += f.y;
            f = __half22float2(*(__half2*)&c.y); v2.z += f.x; v2.w += f.y;
            f = __half22float2(*(__half2*)&d.x); v3.x += f.x; v3.y += f.y;
            f = __half22float2(*(__half2*)&d.y); v3.z += f.x; v3.w += f.y;
        }
        for (; j < end; ++j) {
            int s0 = __ldg(ci + j);
            uint2 a = __ldg((const uint2*)(x + (size_t)s0 * C) + lane);
            float2 f;
            f = __half22float2(*(__half2*)&a.x); v0.x += f.x; v0.y += f.y;
            f = __half22float2(*(__half2*)&a.y); v0.z += f.x; v0.w += f.y;
        }
        int cdeg = end - beg;
        float sc = 1.0f / (float)(cdeg > 1 ? cdeg : 1);
        float r0 = (v0.x + v1.x + v2.x + v3.x) * sc;
        float r1 = (v0.y + v1.y + v2.y + v3.y) * sc;
        float r2 = (v0.z + v1.z + v2.z + v3.z) * sc;
        float r3 = (v0.w + v1.w + v2.w + v3.w) * sc;
        uint2 wv;
        *(__half2*)&wv.x = __floats2half2_rn(r0, r1);
        *(__half2*)&wv.y = __floats2half2_rn(r2, r3);
        *((uint2*)(out + (size_t)node * C) + lane) = wv;
    }
}

// ================ tf32 mma.sync GEMM (fp16 A source) + bias + LN + ReLU ================
// Software-pipelined: next term's A/B tiles prefetched to registers during MMA.
// CTA tile 128x128, K=128; 8 warps 2M x 4N; warp 64x32 via m16n8k8 tf32.
// Padded fragment layouts: A ks-stride 1028, B nt-stride 70 (2-way STS).

__device__ __forceinline__ uint32_t f2tf32(float x) {
    uint32_t o; asm("cvt.rna.tf32.f32 %0, %1;" : "=r"(o) : "f"(x)); return o;
}

#define MMA_TF32(d, a, b)                                                       \
    asm volatile("mma.sync.aligned.m16n8k8.row.col.f32.tf32.tf32.f32 "          \
                 "{%0,%1,%2,%3}, {%4,%5,%6,%7}, {%8,%9}, {%0,%1,%2,%3};"        \
                 : "+f"((d)[0]), "+f"((d)[1]), "+f"((d)[2]), "+f"((d)[3])       \
                 : "r"((a).x), "r"((a).y), "r"((a).z), "r"((a).w),              \
                   "r"((b).x), "r"((b).y))

// SMEM layout (bytes)
#define SM_A      0          // 16 ks x 1028 uint32 = 65792 B
#define SM_B      65792      // 16 ks x 16 nt x 70 uint32 = 71680 B
#define SM_PART   137472     // 128 rows x 4 warps x float2 = 4KB
#define SM_STAT   141568     // 128 x float2 (mu, rs) = 1KB
#define SM_BIAS   142592     // 128 f32
#define SM_LNW    143104
#define SM_LNB    143616
#define GEMM_SMEM 144128

#define GEMM_GRID 782        // ceil(100000 / 128)

// A uint32 idx = ks*1028 + mt*128 + (m&7)*16 + e*4 + slot,
//   slot = ((m>>3)&1) | (((k>>2)&1)<<1), ks=k>>3, mt=m>>4, e=k&3.
// B uint32 idx = (ks*16+nt)*70 + (n&7)*8 + (k&3)*2 + ((k>>2)&1).

__device__ __forceinline__ void ldg_Ah(uint2* pa, const __half* __restrict__ A,
                                       int nodeBase, int N, int t)
{
#pragma unroll
    for (int i = 0; i < 16; ++i) {
        int f = t + i * 256;
        int m = f >> 5, k4 = f & 31;
        int node = nodeBase + m;
        pa[i] = (node < N) ? __ldg((const uint2*)(A + (size_t)node * C) + k4)
                           : make_uint2(0u, 0u);
    }
}

__device__ __forceinline__ void sts_Ah(uint32_t* sA, const uint2* pa, int t)
{
#pragma unroll
    for (int i = 0; i < 16; ++i) {
        int f = t + i * 256;
        int m = f >> 5, k4 = f & 31;
        int ks = k4 >> 1;
        int mt = m >> 4;
        int slot = ((m >> 3) & 1) | ((k4 & 1) << 1);
        int base = ks * 1028 + mt * 128 + ((m & 7) << 4) + slot;
        float2 f01 = __half22float2(*(__half2*)&pa[i].x);
        float2 f23 = __half22float2(*(__half2*)&pa[i].y);
        sA[base + 0 * 4] = f2tf32(f01.x);
        sA[base + 1 * 4] = f2tf32(f01.y);
        sA[base + 2 * 4] = f2tf32(f23.x);
        sA[base + 3 * 4] = f2tf32(f23.y);
    }
}

__device__ __forceinline__ void ldg_B(float4* pb, const float* __restrict__ W, int t)
{
#pragma unroll
    for (int i = 0; i < 16; ++i) pb[i] = __ldg((const float4*)W + t + i * 256);
}

__device__ __forceinline__ void sts_B(uint32_t* sB, const float4* pb, int t)
{
#pragma unroll
    for (int i = 0; i < 16; ++i) {
        int f = t + i * 256;
        int k = f >> 5, n4 = f & 31;
        int ks = k >> 3;
        int nt = n4 >> 1;
        int slot = (k >> 2) & 1;
        int n0_7 = (n4 & 1) << 2;
        int base = (ks * 16 + nt) * 70 + (k & 3) * 2 + slot;
        sB[base + (n0_7 + 0) * 8] = f2tf32(pb[i].x);
        sB[base + (n0_7 + 1) * 8] = f2tf32(pb[i].y);
        sB[base + (n0_7 + 2) * 8] = f2tf32(pb[i].z);
        sB[base + (n0_7 + 3) * 8] = f2tf32(pb[i].w);
    }
}

template <int NTERMS, bool HOUT>
__global__ void __launch_bounds__(256) gemm_mma(
    const __half* __restrict__ A0, const float* __restrict__ W0,
    const __half* __restrict__ A1, const float* __restrict__ W1,
    const __half* __restrict__ A2, const float* __restrict__ W2,
    const float* __restrict__ bias0, const float* __restrict__ bias1,
    const float* __restrict__ lnw, const float* __restrict__ lnb,
    void* __restrict__ outp, int N)
{
    extern __shared__ char smem[];
    uint32_t* sA = (uint32_t*)(smem + SM_A);
    uint32_t* sB = (uint32_t*)(smem + SM_B);
    float2* sPart = (float2*)(smem + SM_PART);
    float2* sStat = (float2*)(smem + SM_STAT);
    float* sBias  = (float*)(smem + SM_BIAS);
    float* sLnw   = (float*)(smem + SM_LNW);
    float* sLnb   = (float*)(smem + SM_LNB);

    const int t = threadIdx.x;
    const int warp = t >> 5;
    const int lane = t & 31;
    const int wm = warp >> 2;     // 0..1  (M half)
    const int wn = warp & 3;      // 0..3  (N quarter)
    const int nodeBase = blockIdx.x * 128;

    if (t < 128) {
        float b = bias0 ? __ldg(bias0 + t) : 0.f;
        if (bias1) b += __ldg(bias1 + t);
        sBias[t] = b;
        sLnw[t] = __ldg(lnw + t);
        sLnb[t] = __ldg(lnb + t);
    }

    const __half* As[3] = {A0, A1, A2};
    const float*  Ws[3] = {W0, W1, W2};

    float acc[4][4][4];
#pragma unroll
    for (int a = 0; a < 4; ++a)
#pragma unroll
        for (int b = 0; b < 4; ++b)
#pragma unroll
            for (int c = 0; c < 4; ++c) acc[a][b][c] = 0.f;

    const uint4* sA4 = (const uint4*)sA;
    const uint2* sB2 = (const uint2*)sB;

    uint2 pa[16];
    float4 pb[16];
    ldg_Ah(pa, As[0], nodeBase, N, t);
    ldg_B(pb, Ws[0], t);

#pragma unroll 1
    for (int term = 0; term < NTERMS; ++term) {
        if (term > 0) __syncthreads();    // all warps done reading previous tiles
        sts_Ah(sA, pa, t);
        sts_B(sB, pb, t);
        __syncthreads();
        if (term + 1 < NTERMS) {          // prefetch next term behind the MMAs
            ldg_Ah(pa, As[term + 1], nodeBase, N, t);
            ldg_B(pb, Ws[term + 1], t);
        }

#pragma unroll 1
        for (int ks = 0; ks < 16; ++ks) {
            uint4 af[4];
            uint2 bf[4];
#pragma unroll
            for (int mt = 0; mt < 4; ++mt)
                af[mt] = sA4[ks * 257 + (wm * 4 + mt) * 32 + lane];
#pragma unroll
            for (int nt = 0; nt < 4; ++nt)
                bf[nt] = sB2[(ks * 16 + wn * 4 + nt) * 35 + lane];
#pragma unroll
            for (int mt = 0; mt < 4; ++mt)
#pragma unroll
                for (int nt = 0; nt < 4; ++nt)
                    MMA_TF32(acc[mt][nt], af[mt], bf[nt]);
        }
    }

    // ---------------- epilogue: bias + LayerNorm + ReLU ----------------
#pragma unroll
    for (int mt = 0; mt < 4; ++mt) {
#pragma unroll
        for (int hi = 0; hi < 2; ++hi) {
            float s = 0.f, q = 0.f;
#pragma unroll
            for (int nt = 0; nt < 4; ++nt) {
#pragma unroll
                for (int e = 0; e < 2; ++e) {
                    int col = (wn * 4 + nt) * 8 + (lane & 3) * 2 + e;
                    float v = acc[mt][nt][hi * 2 + e] + sBias[col];
                    s += v; q += v * v;
                }
            }
            s += __shfl_xor_sync(0xffffffffu, s, 1);
            q += __shfl_xor_sync(0xffffffffu, q, 1);
            s += __shfl_xor_sync(0xffffffffu, s, 2);
            q += __shfl_xor_sync(0xffffffffu, q, 2);
            if ((lane & 3) == 0) {
                int row = (wm * 4 + mt) * 16 + hi * 8 + (lane >> 2);
                sPart[row * 4 + wn] = make_float2(s, q);
            }
        }
    }
    __syncthreads();
    if (t < 128) {
        float2 p0 = sPart[t * 4 + 0], p1 = sPart[t * 4 + 1];
        float2 p2 = sPart[t * 4 + 2], p3 = sPart[t * 4 + 3];
        float s = p0.x + p1.x + p2.x + p3.x;
        float q = p0.y + p1.y + p2.y + p3.y;
        float mu = s * (1.0f / C);
        float var = q * (1.0f / C) - mu * mu;
        sStat[t] = make_float2(mu, rsqrtf(var + 1e-5f));
    }
    __syncthreads();

#pragma unroll
    for (int mt = 0; mt < 4; ++mt) {
#pragma unroll
        for (int hi = 0; hi < 2; ++hi) {
            int row = (wm * 4 + mt) * 16 + hi * 8 + (lane >> 2);
            int node = nodeBase + row;
            if (node < N) {
                float2 st = sStat[row];
#pragma unroll
                for (int nt = 0; nt < 4; ++nt) {
                    int col = (wn * 4 + nt) * 8 + (lane & 3) * 2;
                    float v0 = acc[mt][nt][hi * 2 + 0] + sBias[col];
                    float v1 = acc[mt][nt][hi * 2 + 1] + sBias[col + 1];
                    float o0 = fmaxf((v0 - st.x) * st.y * sLnw[col]     + sLnb[col],     0.f);
                    float o1 = fmaxf((v1 - st.x) * st.y * sLnw[col + 1] + sLnb[col + 1], 0.f);
                    if (HOUT) {
                        __half* o = (__half*)outp + (size_t)node * C + col;
                        *(__half2*)o = __floats2half2_rn(o0, o1);
                    } else {
                        float* o = (float*)outp + (size_t)node * C + col;
                        *(float2*)o = make_float2(o0, o1);
                    }
                }
            }
        }
    }
}

// ---------------- host launcher (single stream) ----------------
extern "C" void kernel_launch(void* const* d_in, const int* in_sizes, int n_in,
                              void* d_out, int out_size)
{
    const float* x_user = (const float*)d_in[0];
    const float* x_item = (const float*)d_in[1];
    const int*   ei_ui  = (const int*)d_in[2];
    const int*   ei_iu  = (const int*)d_in[3];
    const int*   ei_uu  = (const int*)d_in[4];
    const float* Wl     = (const float*)d_in[5];
    const float* bl     = (const float*)d_in[6];
    const float* Wr     = (const float*)d_in[7];
    const float* ln_w   = (const float*)d_in[8];
    const float* ln_b   = (const float*)d_in[9];
    float* out = (float*)d_out;

    void *phu_, *phi_, *phxu_, *phxi_, *phagg_, *pcnt_, *pws_, *prp_, *pci_, *pcur_;
    cudaGetSymbolAddress(&phu_, g_hu);
    cudaGetSymbolAddress(&phi_, g_hi);
    cudaGetSymbolAddress(&phxu_, g_hxu);
    cudaGetSymbolAddress(&phxi_, g_hxi);
    cudaGetSymbolAddress(&phagg_, g_hagg);
    cudaGetSymbolAddress(&pcnt_, g_cnt);
    cudaGetSymbolAddress(&pws_, g_wsum);
    cudaGetSymbolAddress(&prp_, g_rowptr);
    cudaGetSymbolAddress(&pci_, g_colidx);
    cudaGetSymbolAddress(&pcur_, g_cur);
    __half* phu  = (__half*)phu_;
    __half* phi  = (__half*)phi_;
    __half* phxu = (__half*)phxu_;
    __half* phxi = (__half*)phxi_;
    __half* phagg = (__half*)phagg_;
    int*   pcnt = (int*)pcnt_;
    float* pws  = (float*)pws_;
    int*   prp  = (int*)prp_;
    int*   pci  = (int*)pci_;
    int*   pcur = (int*)pcur_;

    cudaFuncSetAttribute((const void*)gemm_mma<2, true>,
                         cudaFuncAttributeMaxDynamicSharedMemorySize, GEMM_SMEM);
    cudaFuncSetAttribute((const void*)gemm_mma<3, true>,
                         cudaFuncAttributeMaxDynamicSharedMemorySize, GEMM_SMEM);
    cudaFuncSetAttribute((const void*)gemm_mma<2, false>,
                         cudaFuncAttributeMaxDynamicSharedMemorySize, GEMM_SMEM);
    cudaFuncSetAttribute((const void*)gemm_mma<3, false>,
                         cudaFuncAttributeMaxDynamicSharedMemorySize, GEMM_SMEM);

    const int GATHER_BLOCKS = 4096;   // x3 via blockIdx.y

    // prep: fp16 copies + wsum (independent of CSR)
    cvt2h_k<<<2048, 256>>>((const float4*)x_user, (const float4*)x_item,
                           (uint2*)phu, (uint2*)phi, (long)(NC / 4));
    for (int ll = 0; ll < 2; ++ll)
        addW_k<<<(CC + 255) / 256, 256>>>(Wr + (size_t)(ll * 3 + 1) * CC,
                                          Wr + (size_t)(ll * 3 + 2) * CC,
                                          pws + (size_t)ll * CC, CC);

    // CSR build
    zero2_k<<<128, 256>>>((float4*)pcnt, (long)(3 * N_NODE) / 4,
                          (float4*)pcur, (long)(3 * N_NODE) / 4);
    count3_k<<<dim3(1024, 3), 256>>>(ei_ui + NEDGE, ei_iu + NEDGE, ei_uu + NEDGE,
                                     pcnt, NEDGE);
    scan_k<<<3, SCAN_T>>>(pcnt, prp);
    fill3_k<<<dim3(1024, 3), 256>>>(ei_ui, ei_iu, ei_uu, prp, pcur, pci, NEDGE);

    // ---------------- layer 0 ----------------
    gather3h_k<<<dim3(GATHER_BLOCKS, 3), 256>>>(phu, phi, phu, prp, pci, phagg, N_NODE);

    // item: mean_ui @ Wl[0,0] + bl[0,0] + xi @ Wr[0,0] -> LN(item) -> ReLU -> fp16
    gemm_mma<2, true><<<GEMM_GRID, 256, GEMM_SMEM>>>(
        phagg + 0 * NC, Wl + 0 * CC,
        phi,            Wr + 0 * CC,
        nullptr,        nullptr,
        bl + 0 * C, nullptr, ln_w + 1 * C, ln_b + 1 * C,
        phxi, N_NODE);

    // user: mean_iu@Wl[0,1] + mean_uu@Wl[0,2] + xu@wsum0 + biases -> fp16
    gemm_mma<3, true><<<GEMM_GRID, 256, GEMM_SMEM>>>(
        phagg + 1 * NC, Wl + 1 * CC,
        phagg + 2 * NC, Wl + 2 * CC,
        phu,            pws + 0 * CC,
        bl + 1 * C, bl + 2 * C, ln_w + 0 * C, ln_b + 0 * C,
        phxu, N_NODE);

    // ---------------- layer 1 ----------------
    gather3h_k<<<dim3(GATHER_BLOCKS, 3), 256>>>(phxu, phxi, phxu, prp, pci, phagg, N_NODE);

    // item l1 -> out[NC:2NC] fp32
    gemm_mma<2, false><<<GEMM_GRID, 256, GEMM_SMEM>>>(
        phagg + 0 * NC, Wl + (size_t)(1 * 3 + 0) * CC,
        phxi,           Wr + (size_t)(1 * 3 + 0) * CC,
        nullptr,        nullptr,
        bl + (size_t)(1 * 3 + 0) * C, nullptr,
        ln_w + (size_t)(1 * 2 + 1) * C, ln_b + (size_t)(1 * 2 + 1) * C,
        out + NC, N_NODE);

    // user l1 -> out[0:NC] fp32
    gemm_mma<3, false><<<GEMM_GRID, 256, GEMM_SMEM>>>(
        phagg + 1 * NC, Wl + (size_t)(1 * 3 + 1) * CC,
        phagg + 2 * NC, Wl + (size_t)(1 * 3 + 2) * CC,
        phxu,           pws + 1 * CC,
        bl + (size_t)(1 * 3 + 1) * C, bl + (size_t)(1 * 3 + 2) * C,
        ln_w + (size_t)(1 * 2 + 0) * C, ln_b + (size_t)(1 * 2 + 0) * C,
        out, N_NODE);
}

// round 14
// speedup vs baseline: 3.3882x; 1.2103x over previous
#include <cuda_runtime.h>
#include <cuda_fp16.h>
#include <cstdint>

#define N_NODE 100000        // N_USER == N_ITEM == 100000
#define NEDGE  1000000
#define C      128
#define CC     (C * C)
#define NC     ((size_t)N_NODE * C)

// ---------------- device scratch (allowed: __device__ globals) ----------------
__device__ __align__(16) __half g_hu[NC];           // fp16 copy of x_user
__device__ __align__(16) __half g_hi[NC];           // fp16 copy of x_item
__device__ __align__(16) __half g_hxu[NC];          // layer-0 user output (fp16)
__device__ __align__(16) __half g_hxi[NC];          // layer-0 item output (fp16)
__device__ __align__(16) __half g_hagg[3][NC];      // gathered means (fp16)
__device__ __align__(16) int    g_cnt[3 * N_NODE];
__device__ __align__(16) float  g_wsum[2 * CC];     // Wr[l,1]+Wr[l,2] per layer
__device__ __align__(16) int    g_rowptr[3 * (N_NODE + 1)];
__device__ __align__(16) int    g_colidx[3 * NEDGE];
__device__ __align__(16) int    g_cur[3 * N_NODE];

// ---------------- utility kernels ----------------
__global__ void zero2_k(float4* __restrict__ a, long na4,
                        float4* __restrict__ b, long nb4) {
    long i = (long)blockIdx.x * blockDim.x + threadIdx.x;
    long st = (long)gridDim.x * blockDim.x;
    float4 z = make_float4(0.f, 0.f, 0.f, 0.f);
    for (long j = i; j < na4; j += st) a[j] = z;
    for (long j = i; j < nb4; j += st) b[j] = z;
}

// fp32 -> fp16 copies of both feature matrices
__global__ void cvt2h_k(const float4* __restrict__ xu, const float4* __restrict__ xi,
                        uint2* __restrict__ hu, uint2* __restrict__ hi, long n4) {
    long i = (long)blockIdx.x * blockDim.x + threadIdx.x;
    long st = (long)gridDim.x * blockDim.x;
    for (long j = i; j < n4; j += st) {
        float4 a = xu[j];
        uint2 w;
        *(__half2*)&w.x = __floats2half2_rn(a.x, a.y);
        *(__half2*)&w.y = __floats2half2_rn(a.z, a.w);
        hu[j] = w;
        float4 b = xi[j];
        *(__half2*)&w.x = __floats2half2_rn(b.x, b.y);
        *(__half2*)&w.y = __floats2half2_rn(b.z, b.w);
        hi[j] = w;
    }
}

// all 3 edge types in one launch: blockIdx.y selects type
__global__ void count3_k(const int* __restrict__ d0, const int* __restrict__ d1,
                         const int* __restrict__ d2, int* __restrict__ cnt, int E) {
    const int* dst = (blockIdx.y == 0) ? d0 : (blockIdx.y == 1) ? d1 : d2;
    int* c = cnt + blockIdx.y * N_NODE;
    int i = blockIdx.x * blockDim.x + threadIdx.x;
    int st = gridDim.x * blockDim.x;
    for (; i < E; i += st) atomicAdd(c + dst[i], 1);
}

__global__ void fill3_k(const int* __restrict__ e0, const int* __restrict__ e1,
                        const int* __restrict__ e2, const int* __restrict__ rowptr,
                        int* __restrict__ cur, int* __restrict__ col, int E) {
    const int* ei = (blockIdx.y == 0) ? e0 : (blockIdx.y == 1) ? e1 : e2;
    const int* rp = rowptr + blockIdx.y * (N_NODE + 1);
    int* cu = cur + blockIdx.y * N_NODE;
    int* co = col + blockIdx.y * NEDGE;
    int i = blockIdx.x * blockDim.x + threadIdx.x;
    int st = gridDim.x * blockDim.x;
    for (; i < E; i += st) {
        int s = ei[i];
        int d = ei[E + i];
        int pos = rp[d] + atomicAdd(cu + d, 1);
        co[pos] = s;
    }
}

__global__ void addW_k(const float* __restrict__ a, const float* __restrict__ b,
                       float* __restrict__ o, int n) {
    int i = blockIdx.x * blockDim.x + threadIdx.x;
    if (i < n) o[i] = a[i] + b[i];
}

// exclusive scan of one edge type's counts -> rowptr. One block per type.
#define SCAN_T 1024
__global__ void __launch_bounds__(SCAN_T) scan_k(const int* __restrict__ cnt,
                                                 int* __restrict__ rowptr) {
    int type = blockIdx.x;
    const int* c = cnt + type * N_NODE;
    int* rp = rowptr + type * (N_NODE + 1);
    __shared__ int part[SCAN_T];
    int t = threadIdx.x;
    const int chunk = (N_NODE + SCAN_T - 1) / SCAN_T;   // 98
    int beg = t * chunk;
    int end = beg + chunk; if (end > N_NODE) end = N_NODE;
    int s = 0;
    for (int i = beg; i < end; ++i) s += c[i];
    part[t] = s;
    __syncthreads();
    for (int off = 1; off < SCAN_T; off <<= 1) {
        int v = (t >= off) ? part[t - off] : 0;
        __syncthreads();
        part[t] += v;
        __syncthreads();
    }
    int prefix = (t == 0) ? 0 : part[t - 1];
    for (int i = beg; i < end; ++i) {
        rp[i] = prefix;
        prefix += c[i];
    }
    if (t == SCAN_T - 1) rp[N_NODE] = prefix;
}

// ---------------- CSR gather-mean (fp16 in / fp16 out), 3 types per launch ----------
__global__ void __launch_bounds__(256) gather3h_k(
    const __half* __restrict__ x0, const __half* __restrict__ x1,
    const __half* __restrict__ x2,
    const int* __restrict__ rowptr, const int* __restrict__ colidx,
    __half* __restrict__ agg, int n)
{
    int type = blockIdx.y;
    const __half* x = (type == 0) ? x0 : (type == 1) ? x1 : x2;
    const int* rp = rowptr + type * (N_NODE + 1);
    const int* ci = colidx + type * NEDGE;
    __half* out = agg + (size_t)type * NC;

    int lane = threadIdx.x & 31;
    int w = (blockIdx.x * blockDim.x + threadIdx.x) >> 5;
    int nw = (gridDim.x * blockDim.x) >> 5;
    for (int node = w; node < n; node += nw) {
        int beg = __ldg(rp + node);
        int end = __ldg(rp + node + 1);
        float4 v0 = make_float4(0.f, 0.f, 0.f, 0.f);
        float4 v1 = v0, v2 = v0, v3 = v0;
        int j = beg;
        for (; j + 3 < end; j += 4) {
            int s0 = __ldg(ci + j);
            int s1 = __ldg(ci + j + 1);
            int s2 = __ldg(ci + j + 2);
            int s3 = __ldg(ci + j + 3);
            uint2 a = __ldg((const uint2*)(x + (size_t)s0 * C) + lane);
            uint2 b = __ldg((const uint2*)(x + (size_t)s1 * C) + lane);
            uint2 c = __ldg((const uint2*)(x + (size_t)s2 * C) + lane);
            uint2 d = __ldg((const uint2*)(x + (size_t)s3 * C) + lane);
            float2 f;
            f = __half22float2(*(__half2*)&a.x); v0.x += f.x; v0.y += f.y;
            f = __half22float2(*(__half2*)&a.y); v0.z += f.x; v0.w += f.y;
            f = __half22float2(*(__half2*)&b.x); v1.x += f.x; v1.y += f.y;
            f = __half22float2(*(__half2*)&b.y); v1.z += f.x; v1.w += f.y;
            f = __half22float2(*(__half2*)&c.x); v2.x += f.x; v2.y += f.y;
            f = __half22float2(*(__half2*)&c.y); v2.z += f.x; v2.w += f.y;
            f = __half22float2(*(__half2*)&d.x); v3.x += f.x; v3.y += f.y;
            f = __half22float2(*(__half2*)&d.y); v3.z += f.x; v3.w += f.y;
        }
        for (; j < end; ++j) {
            int s0 = __ldg(ci + j);
            uint2 a = __ldg((const uint2*)(x + (size_t)s0 * C) + lane);
            float2 f;
            f = __half22float2(*(__half2*)&a.x); v0.x += f.x; v0.y += f.y;
            f = __half22float2(*(__half2*)&a.y); v0.z += f.x; v0.w += f.y;
        }
        int cdeg = end - beg;
        float sc = 1.0f / (float)(cdeg > 1 ? cdeg : 1);
        float r0 = (v0.x + v1.x + v2.x + v3.x) * sc;
        float r1 = (v0.y + v1.y + v2.y + v3.y) * sc;
        float r2 = (v0.z + v1.z + v2.z + v3.z) * sc;
        float r3 = (v0.w + v1.w + v2.w + v3.w) * sc;
        uint2 wv;
        *(__half2*)&wv.x = __floats2half2_rn(r0, r1);
        *(__half2*)&wv.y = __floats2half2_rn(r2, r3);
        *((uint2*)(out + (size_t)node * C) + lane) = wv;
    }
}

// ================ fp16 mma.sync GEMM (fp32 accum) + bias + LN + ReLU ================
// CTA tile 128x128, K=128; 8 warps 2M x 4N; warp 64x32 via m16n8k16.f32.f16.f16.f32.
// 2 CTAs/SM (73KB smem, <=128 regs): cross-CTA overlap hides staging latency.
//
// A fragment word (m, k-pair p=k>>1): lane=(m&7)*4+(p&3),
//   slot = ((m>>3)&1) | (((p>>2)&1)<<1); idx32 = ks*1028 + mt*128 + lane*4 + slot.
// B fragment word (n, p): lane=(n&7)*4+(p&3), slot=(p>>2)&1;
//   idx32 = (ks*16+nt)*66 + lane*2 + slot.   (ks=k>>4, mt=m>>4, nt=n>>3)

#define MMA_F16(d, a, b)                                                        \
    asm volatile("mma.sync.aligned.m16n8k16.row.col.f32.f16.f16.f32 "           \
                 "{%0,%1,%2,%3}, {%4,%5,%6,%7}, {%8,%9}, {%0,%1,%2,%3};"        \
                 : "+f"((d)[0]), "+f"((d)[1]), "+f"((d)[2]), "+f"((d)[3])       \
                 : "r"((a).x), "r"((a).y), "r"((a).z), "r"((a).w),              \
                   "r"((b).x), "r"((b).y))

// SMEM layout (bytes)
#define SM_A      0          // 8 ks x 1028 uint32 = 32896 B
#define SM_B      32896      // 8 ks x 16 nt x 66 uint32 = 33792 B -> ends 66688
#define SM_PART   66688      // 128 rows x 4 warps x float2 = 4096
#define SM_STAT   70784      // 128 x float2 = 1024
#define SM_BIAS   71808      // 128 f32
#define SM_LNW    72320
#define SM_LNB    72832
#define GEMM_SMEM 73344

#define GEMM_GRID 782        // ceil(100000 / 128)

// stage A (fp16 source): thread copies uint2 (4 halfs) -> two 32-bit smem words
__device__ __forceinline__ void stage_A16(uint32_t* sA, const __half* __restrict__ A,
                                          int nodeBase, int N, int t)
{
#pragma unroll
    for (int i = 0; i < 16; ++i) {
        int f = t + i * 256;              // m = f>>5, k4 = f&31 (k = 4*k4..4*k4+3)
        int m = f >> 5, k4 = f & 31;
        int node = nodeBase + m;
        uint2 v = (node < N) ? __ldg((const uint2*)(A + (size_t)node * C) + k4)
                             : make_uint2(0u, 0u);
        int ks = k4 >> 2;
        int mt = m >> 4;
        uint32_t wrd[2] = {v.x, v.y};
#pragma unroll
        for (int j = 0; j < 2; ++j) {
            int p = 2 * k4 + j;           // k-pair index, global: p&7 within ks
            int lane = (m & 7) * 4 + (p & 3);
            int slot = ((m >> 3) & 1) | ((((p >> 2) & 1)) << 1);
            sA[ks * 1028 + mt * 128 + lane * 4 + slot] = wrd[j];
        }
    }
}

// stage B from fp32 W [k][n] row-major: pair rows (2k', 2k'+1), pack half2{Wk,Wk+1}
__device__ __forceinline__ void stage_B16(uint32_t* sB, const float* __restrict__ W, int t)
{
#pragma unroll
    for (int i = 0; i < 8; ++i) {
        int f = t + i * 256;              // pair index: kp = f>>5 (0..63), n4 = f&31
        int kp = f >> 5, n4 = f & 31;
        float4 w0 = __ldg((const float4*)W + (2 * kp) * 32 + n4);
        float4 w1 = __ldg((const float4*)W + (2 * kp + 1) * 32 + n4);
        float a0[4] = {w0.x, w0.y, w0.z, w0.w};
        float a1[4] = {w1.x, w1.y, w1.z, w1.w};
        int ks = kp >> 3;
        int slot = (kp >> 2) & 1;
        int lane_k = kp & 3;
#pragma unroll
        for (int e = 0; e < 4; ++e) {
            int n = 4 * n4 + e;
            int nt = n >> 3;
            int lane = (n & 7) * 4 + lane_k;
            uint32_t wrd;
            *(__half2*)&wrd = __floats2half2_rn(a0[e], a1[e]);
            sB[(ks * 16 + nt) * 66 + lane * 2 + slot] = wrd;
        }
    }
}

template <int NTERMS, bool HOUT>
__global__ void __launch_bounds__(256, 2) gemm_mma(
    const __half* __restrict__ A0, const float* __restrict__ W0,
    const __half* __restrict__ A1, const float* __restrict__ W1,
    const __half* __restrict__ A2, const float* __restrict__ W2,
    const float* __restrict__ bias0, const float* __restrict__ bias1,
    const float* __restrict__ lnw, const float* __restrict__ lnb,
    void* __restrict__ outp, int N)
{
    extern __shared__ char smem[];
    uint32_t* sA = (uint32_t*)(smem + SM_A);
    uint32_t* sB = (uint32_t*)(smem + SM_B);
    float2* sPart = (float2*)(smem + SM_PART);
    float2* sStat = (float2*)(smem + SM_STAT);
    float* sBias  = (float*)(smem + SM_BIAS);
    float* sLnw   = (float*)(smem + SM_LNW);
    float* sLnb   = (float*)(smem + SM_LNB);

    const int t = threadIdx.x;
    const int warp = t >> 5;
    const int lane = t & 31;
    const int wm = warp >> 2;     // 0..1  (M half)
    const int wn = warp & 3;      // 0..3  (N quarter)
    const int nodeBase = blockIdx.x * 128;

    if (t < 128) {
        float b = bias0 ? __ldg(bias0 + t) : 0.f;
        if (bias1) b += __ldg(bias1 + t);
        sBias[t] = b;
        sLnw[t] = __ldg(lnw + t);
        sLnb[t] = __ldg(lnb + t);
    }

    const __half* As[3] = {A0, A1, A2};
    const float*  Ws[3] = {W0, W1, W2};

    float acc[4][4][4];
#pragma unroll
    for (int a = 0; a < 4; ++a)
#pragma unroll
        for (int b = 0; b < 4; ++b)
#pragma unroll
            for (int c = 0; c < 4; ++c) acc[a][b][c] = 0.f;

    const uint4* sA4 = (const uint4*)sA;
    const uint2* sB2 = (const uint2*)sB;

#pragma unroll 1
    for (int term = 0; term < NTERMS; ++term) {
        if (term > 0) __syncthreads();    // all warps done reading previous tiles
        stage_A16(sA, As[term], nodeBase, N, t);
        stage_B16(sB, Ws[term], t);
        __syncthreads();

#pragma unroll 1
        for (int ks = 0; ks < 8; ++ks) {
            uint4 af[4];
            uint2 bf[4];
#pragma unroll
            for (int mt = 0; mt < 4; ++mt)
                af[mt] = sA4[ks * 257 + (wm * 4 + mt) * 32 + lane];
#pragma unroll
            for (int nt = 0; nt < 4; ++nt)
                bf[nt] = sB2[(ks * 16 + wn * 4 + nt) * 33 + lane];
#pragma unroll
            for (int mt = 0; mt < 4; ++mt)
#pragma unroll
                for (int nt = 0; nt < 4; ++nt)
                    MMA_F16(acc[mt][nt], af[mt], bf[nt]);
        }
    }

    // ---------------- epilogue: bias + LayerNorm + ReLU ----------------
#pragma unroll
    for (int mt = 0; mt < 4; ++mt) {
#pragma unroll
        for (int hi = 0; hi < 2; ++hi) {
            float s = 0.f, q = 0.f;
#pragma unroll
            for (int nt = 0; nt < 4; ++nt) {
#pragma unroll
                for (int e = 0; e < 2; ++e) {
                    int col = (wn * 4 + nt) * 8 + (lane & 3) * 2 + e;
                    float v = acc[mt][nt][hi * 2 + e] + sBias[col];
                    s += v; q += v * v;
                }
            }
            s += __shfl_xor_sync(0xffffffffu, s, 1);
            q += __shfl_xor_sync(0xffffffffu, q, 1);
            s += __shfl_xor_sync(0xffffffffu, s, 2);
            q += __shfl_xor_sync(0xffffffffu, q, 2);
            if ((lane & 3) == 0) {
                int row = (wm * 4 + mt) * 16 + hi * 8 + (lane >> 2);
                sPart[row * 4 + wn] = make_float2(s, q);
            }
        }
    }
    __syncthreads();
    if (t < 128) {
        float2 p0 = sPart[t * 4 + 0], p1 = sPart[t * 4 + 1];
        float2 p2 = sPart[t * 4 + 2], p3 = sPart[t * 4 + 3];
        float s = p0.x + p1.x + p2.x + p3.x;
        float q = p0.y + p1.y + p2.y + p3.y;
        float mu = s * (1.0f / C);
        float var = q * (1.0f / C) - mu * mu;
        sStat[t] = make_float2(mu, rsqrtf(var + 1e-5f));
    }
    __syncthreads();

#pragma unroll
    for (int mt = 0; mt < 4; ++mt) {
#pragma unroll
        for (int hi = 0; hi < 2; ++hi) {
            int row = (wm * 4 + mt) * 16 + hi * 8 + (lane >> 2);
            int node = nodeBase + row;
            if (node < N) {
                float2 st = sStat[row];
#pragma unroll
                for (int nt = 0; nt < 4; ++nt) {
                    int col = (wn * 4 + nt) * 8 + (lane & 3) * 2;
                    float v0 = acc[mt][nt][hi * 2 + 0] + sBias[col];
                    float v1 = acc[mt][nt][hi * 2 + 1] + sBias[col + 1];
                    float o0 = fmaxf((v0 - st.x) * st.y * sLnw[col]     + sLnb[col],     0.f);
                    float o1 = fmaxf((v1 - st.x) * st.y * sLnw[col + 1] + sLnb[col + 1], 0.f);
                    if (HOUT) {
                        __half* o = (__half*)outp + (size_t)node * C + col;
                        *(__half2*)o = __floats2half2_rn(o0, o1);
                    } else {
                        float* o = (float*)outp + (size_t)node * C + col;
                        *(float2*)o = make_float2(o0, o1);
                    }
                }
            }
        }
    }
}

// ---------------- host launcher (single stream) ----------------
extern "C" void kernel_launch(void* const* d_in, const int* in_sizes, int n_in,
                              void* d_out, int out_size)
{
    const float* x_user = (const float*)d_in[0];
    const float* x_item = (const float*)d_in[1];
    const int*   ei_ui  = (const int*)d_in[2];
    const int*   ei_iu  = (const int*)d_in[3];
    const int*   ei_uu  = (const int*)d_in[4];
    const float* Wl     = (const float*)d_in[5];
    const float* bl     = (const float*)d_in[6];
    const float* Wr     = (const float*)d_in[7];
    const float* ln_w   = (const float*)d_in[8];
    const float* ln_b   = (const float*)d_in[9];
    float* out = (float*)d_out;

    void *phu_, *phi_, *phxu_, *phxi_, *phagg_, *pcnt_, *pws_, *prp_, *pci_, *pcur_;
    cudaGetSymbolAddress(&phu_, g_hu);
    cudaGetSymbolAddress(&phi_, g_hi);
    cudaGetSymbolAddress(&phxu_, g_hxu);
    cudaGetSymbolAddress(&phxi_, g_hxi);
    cudaGetSymbolAddress(&phagg_, g_hagg);
    cudaGetSymbolAddress(&pcnt_, g_cnt);
    cudaGetSymbolAddress(&pws_, g_wsum);
    cudaGetSymbolAddress(&prp_, g_rowptr);
    cudaGetSymbolAddress(&pci_, g_colidx);
    cudaGetSymbolAddress(&pcur_, g_cur);
    __half* phu  = (__half*)phu_;
    __half* phi  = (__half*)phi_;
    __half* phxu = (__half*)phxu_;
    __half* phxi = (__half*)phxi_;
    __half* phagg = (__half*)phagg_;
    int*   pcnt = (int*)pcnt_;
    float* pws  = (float*)pws_;
    int*   prp  = (int*)prp_;
    int*   pci  = (int*)pci_;
    int*   pcur = (int*)pcur_;

    cudaFuncSetAttribute((const void*)gemm_mma<2, true>,
                         cudaFuncAttributeMaxDynamicSharedMemorySize, GEMM_SMEM);
    cudaFuncSetAttribute((const void*)gemm_mma<3, true>,
                         cudaFuncAttributeMaxDynamicSharedMemorySize, GEMM_SMEM);
    cudaFuncSetAttribute((const void*)gemm_mma<2, false>,
                         cudaFuncAttributeMaxDynamicSharedMemorySize, GEMM_SMEM);
    cudaFuncSetAttribute((const void*)gemm_mma<3, false>,
                         cudaFuncAttributeMaxDynamicSharedMemorySize, GEMM_SMEM);

    const int GATHER_BLOCKS = 4096;   // x3 via blockIdx.y

    // prep: fp16 copies + wsum (independent of CSR)
    cvt2h_k<<<2048, 256>>>((const float4*)x_user, (const float4*)x_item,
                           (uint2*)phu, (uint2*)phi, (long)(NC / 4));
    for (int ll = 0; ll < 2; ++ll)
        addW_k<<<(CC + 255) / 256, 256>>>(Wr + (size_t)(ll * 3 + 1) * CC,
                                          Wr + (size_t)(ll * 3 + 2) * CC,
                                          pws + (size_t)ll * CC, CC);

    // CSR build
    zero2_k<<<128, 256>>>((float4*)pcnt, (long)(3 * N_NODE) / 4,
                          (float4*)pcur, (long)(3 * N_NODE) / 4);
    count3_k<<<dim3(1024, 3), 256>>>(ei_ui + NEDGE, ei_iu + NEDGE, ei_uu + NEDGE,
                                     pcnt, NEDGE);
    scan_k<<<3, SCAN_T>>>(pcnt, prp);
    fill3_k<<<dim3(1024, 3), 256>>>(ei_ui, ei_iu, ei_uu, prp, pcur, pci, NEDGE);

    // ---------------- layer 0 ----------------
    gather3h_k<<<dim3(GATHER_BLOCKS, 3), 256>>>(phu, phi, phu, prp, pci, phagg, N_NODE);

    // item: mean_ui @ Wl[0,0] + bl[0,0] + xi @ Wr[0,0] -> LN(item) -> ReLU -> fp16
    gemm_mma<2, true><<<GEMM_GRID, 256, GEMM_SMEM>>>(
        phagg + 0 * NC, Wl + 0 * CC,
        phi,            Wr + 0 * CC,
        nullptr,        nullptr,
        bl + 0 * C, nullptr, ln_w + 1 * C, ln_b + 1 * C,
        phxi, N_NODE);

    // user: mean_iu@Wl[0,1] + mean_uu@Wl[0,2] + xu@wsum0 + biases -> fp16
    gemm_mma<3, true><<<GEMM_GRID, 256, GEMM_SMEM>>>(
        phagg + 1 * NC, Wl + 1 * CC,
        phagg + 2 * NC, Wl + 2 * CC,
        phu,            pws + 0 * CC,
        bl + 1 * C, bl + 2 * C, ln_w + 0 * C, ln_b + 0 * C,
        phxu, N_NODE);

    // ---------------- layer 1 ----------------
    gather3h_k<<<dim3(GATHER_BLOCKS, 3), 256>>>(phxu, phxi, phxu, prp, pci, phagg, N_NODE);

    // item l1 -> out[NC:2NC] fp32
    gemm_mma<2, false><<<GEMM_GRID, 256, GEMM_SMEM>>>(
        phagg + 0 * NC, Wl + (size_t)(1 * 3 + 0) * CC,
        phxi,           Wr + (size_t)(1 * 3 + 0) * CC,
        nullptr,        nullptr,
        bl + (size_t)(1 * 3 + 0) * C, nullptr,
        ln_w + (size_t)(1 * 2 + 1) * C, ln_b + (size_t)(1 * 2 + 1) * C,
        out + NC, N_NODE);

    // user l1 -> out[0:NC] fp32
    gemm_mma<3, false><<<GEMM_GRID, 256, GEMM_SMEM>>>(
        phagg + 1 * NC, Wl + (size_t)(1 * 3 + 1) * CC,
        phagg + 2 * NC, Wl + (size_t)(1 * 3 + 2) * CC,
        phxu,           pws + 1 * CC,
        bl + (size_t)(1 * 3 + 1) * C, bl + (size_t)(1 * 3 + 2) * C,
        ln_w + (size_t)(1 * 2 + 0) * C, ln_b + (size_t)(1 * 2 + 0) * C,
        out, N_NODE);
}